// round 1
// baseline (speedup 1.0000x reference)
#include <cuda_runtime.h>

#define NN 50000
#define EE 800000
#define MULC 32
#define SC 5
#define NBC 8
#define HC 64
#define NWC 128

// ---------------- device scratch (static, no allocation) ----------------
__device__ float g_sh1[EE * 3];          // l=1 SH per edge
__device__ float g_eemb[EE * NBC];       // bessel*envelope per edge
__device__ float g_hs[NN * MULC];        // node scalar feats
__device__ float g_hv[NN * 3 * MULC];    // node vector feats, layout [n][i][u]
__device__ float g_hsl[NN * MULC];       // lin1 scalar
__device__ float g_hvl[NN * 3 * MULC];   // lin1 vector, [n][i][u]
__device__ float g_res_s[NN * 2 * MULC];
__device__ float g_res_v[NN * 3 * MULC]; // [n][i][u]
__device__ float g_n0[NN * 2 * MULC];    // scatter accum scalars
__device__ float g_n1[NN * 3 * 2 * MULC];// scatter accum vectors, [n][i][c] c<64

__device__ __forceinline__ float silu(float x) {
    // x * sigmoid(x); exact-enough: __expf rel err ~1e-6 in our range
    return x / (1.0f + __expf(-x));
}

// ---------------- edge precompute: sh1 + bessel*envelope ----------------
__global__ void k_edge_pre(const float* __restrict__ evec) {
    int e = blockIdx.x * blockDim.x + threadIdx.x;
    if (e >= EE) return;
    float x = evec[e * 3 + 0], y = evec[e * 3 + 1], z = evec[e * 3 + 2];
    float r = sqrtf(x * x + y * y + z * z + 1e-12f);
    float ir = 1.0f / r;
    const float SQ3 = 1.7320508075688772f;
    g_sh1[e * 3 + 0] = SQ3 * x * ir;
    g_sh1[e * 3 + 1] = SQ3 * y * ir;
    g_sh1[e * 3 + 2] = SQ3 * z * ir;
    float xr = r * 0.2f;                 // r / R_MAX
    float env = 0.0f;
    if (xr < 1.0f) {
        float x2 = xr * xr, x3 = x2 * xr, x6 = x3 * x3, x7 = x6 * xr, x8 = x7 * xr;
        env = 1.0f - 28.0f * x6 + 48.0f * x7 - 21.0f * x8;  // p=6 polynomial cutoff
    }
    float c = 0.6324555320336759f * ir * env;  // sqrt(2/R_MAX)/r * env
    const float PI_ = 3.14159265358979323846f;
    float arg = PI_ * xr;                      // pi*r/R_MAX
#pragma unroll
    for (int n = 1; n <= NBC; n++)
        g_eemb[e * NBC + n - 1] = c * sinf(arg * (float)n);
}

// ---------------- node embedding ----------------
__global__ void k_node_init(const int* __restrict__ species,
                            const float* __restrict__ embed_w) {
    int idx = blockIdx.x * blockDim.x + threadIdx.x;
    if (idx >= NN * MULC) return;
    int n = idx >> 5, u = idx & 31;
    g_hs[idx] = embed_w[species[n] * MULC + u] * 0.4472135954999579f; // /sqrt(5)
}

// ---------------- per-layer node prep: residual TP + lin1 + zero accums ----------------
template <bool HAS_VEC>
__global__ void k_node_prep(const int* __restrict__ species,
                            const float* __restrict__ w_res_s,
                            const float* __restrict__ w_res_v,
                            const float* __restrict__ w_lin1_s,
                            const float* __restrict__ w_lin1_v, int l) {
    int w = (blockIdx.x * blockDim.x + threadIdx.x) >> 5;
    int lane = threadIdx.x & 31;
    if (w >= NN) return;
    int n = w;
    int spec = species[n];
    const float* Wl1s = w_lin1_s + l * MULC * MULC;
    const float* Wl1v = w_lin1_v + l * MULC * MULC;
    const float* Wrs = w_res_s + l * MULC * SC * 2 * MULC + spec * 2 * MULC;
    const float* Wrv = w_res_v + l * MULC * SC * MULC + spec * MULC;
    float a_hs = 0.f, a_rs0 = 0.f, a_rs1 = 0.f;
    float a_hv0 = 0.f, a_hv1 = 0.f, a_hv2 = 0.f;
    float a_rv0 = 0.f, a_rv1 = 0.f, a_rv2 = 0.f;
#pragma unroll 4
    for (int u = 0; u < MULC; u++) {
        float hsu = g_hs[n * MULC + u];
        a_hs  += hsu * Wl1s[u * MULC + lane];
        a_rs0 += hsu * Wrs[u * SC * 2 * MULC + lane];
        a_rs1 += hsu * Wrs[u * SC * 2 * MULC + MULC + lane];
        if (HAS_VEC) {
            float wv = Wl1v[u * MULC + lane];
            float wr = Wrv[u * SC * MULC + lane];
            float h0 = g_hv[(n * 3 + 0) * MULC + u];
            float h1 = g_hv[(n * 3 + 1) * MULC + u];
            float h2 = g_hv[(n * 3 + 2) * MULC + u];
            a_hv0 += h0 * wv; a_hv1 += h1 * wv; a_hv2 += h2 * wv;
            a_rv0 += h0 * wr; a_rv1 += h1 * wr; a_rv2 += h2 * wr;
        }
    }
    const float IS32 = 0.17677669529663687f;   // 1/sqrt(32)
    const float IS160 = 0.07905694150420949f;  // 1/sqrt(160)
    g_hsl[n * MULC + lane] = a_hs * IS32;
    g_res_s[n * 2 * MULC + lane] = a_rs0 * IS160;
    g_res_s[n * 2 * MULC + MULC + lane] = a_rs1 * IS160;
    g_hvl[(n * 3 + 0) * MULC + lane] = a_hv0 * IS32;
    g_hvl[(n * 3 + 1) * MULC + lane] = a_hv1 * IS32;
    g_hvl[(n * 3 + 2) * MULC + lane] = a_hv2 * IS32;
    g_res_v[(n * 3 + 0) * MULC + lane] = a_rv0 * IS160;
    g_res_v[(n * 3 + 1) * MULC + lane] = a_rv1 * IS160;
    g_res_v[(n * 3 + 2) * MULC + lane] = a_rv2 * IS160;
    // zero scatter accumulators
    g_n0[n * 64 + lane] = 0.f;
    g_n0[n * 64 + 32 + lane] = 0.f;
#pragma unroll
    for (int i = 0; i < 3; i++) {
        g_n1[(n * 3 + i) * 64 + lane] = 0.f;
        g_n1[(n * 3 + i) * 64 + 32 + lane] = 0.f;
    }
}

// ---------------- main edge kernel: radial MLP + TP + scatter ----------------
#define EPW 4
#define PADW 68  // padded row stride (floats) for conflict-free float4 LDS
#define SMEM_FLOATS (512 + 64 * PADW + 128 * PADW + 8 * EPW * 64)

template <bool HAS_VEC>
__global__ void __launch_bounds__(256) k_edge(
    const float* __restrict__ mlp_w0, const float* __restrict__ mlp_w1,
    const float* __restrict__ mlp_w2, const int* __restrict__ senders,
    const int* __restrict__ receivers, int l) {
    extern __shared__ float sm[];
    float* sw0 = sm;                    // [8][64]  scaled by 1/sqrt(8)
    float* sw1t = sm + 512;             // [64][PADW] transposed, scaled 1/8
    float* sw2t = sw1t + 64 * PADW;     // [128][PADW] transposed
    float* sa = sw2t + 128 * PADW;      // [8 warps][EPW][64] activations
    int tid = threadIdx.x;
    {
        const float* w0g = mlp_w0 + l * NBC * HC;
        const float* w1g = mlp_w1 + l * HC * HC;
        const float* w2g = mlp_w2 + l * HC * NWC;
        for (int i = tid; i < NBC * HC; i += 256) sw0[i] = w0g[i] * 0.35355339059327373f;
        for (int i = tid; i < HC * HC; i += 256) {
            int j = i & 63, k = i >> 6;
            sw1t[j * PADW + k] = w1g[k * HC + j] * 0.125f;
        }
        for (int i = tid; i < HC * NWC; i += 256) {
            int j = i & 127, k = i >> 7;
            sw2t[j * PADW + k] = w2g[k * NWC + j];
        }
    }
    __syncthreads();
    int warp = tid >> 5, lane = tid & 31;
    float* wa = sa + warp * (EPW * 64);
    int gw = blockIdx.x * 8 + warp;
    int stride = gridDim.x * 8 * EPW;
    for (int base = gw * EPW; base < EE; base += stride) {
        // -------- layer 1: [8] -> [64], silu --------
#pragma unroll
        for (int e = 0; e < EPW; e++) {
            const float4* ep = reinterpret_cast<const float4*>(g_eemb + (size_t)(base + e) * NBC);
            float4 e0 = ep[0], e1 = ep[1];
            float ee[8] = {e0.x, e0.y, e0.z, e0.w, e1.x, e1.y, e1.z, e1.w};
            float acc0 = 0.f, acc1 = 0.f;
#pragma unroll
            for (int k = 0; k < 8; k++) {
                acc0 += ee[k] * sw0[k * 64 + lane];
                acc1 += ee[k] * sw0[k * 64 + 32 + lane];
            }
            wa[e * 64 + lane] = silu(acc0);
            wa[e * 64 + 32 + lane] = silu(acc1);
        }
        __syncwarp();
        // -------- layer 2: [64] -> [64], silu --------
        float b0[EPW], b1[EPW];
#pragma unroll
        for (int e = 0; e < EPW; e++) { b0[e] = 0.f; b1[e] = 0.f; }
        {
            const float4* r0 = reinterpret_cast<const float4*>(sw1t + lane * PADW);
            const float4* r1 = reinterpret_cast<const float4*>(sw1t + (lane + 32) * PADW);
#pragma unroll
            for (int k4 = 0; k4 < 16; k4++) {
                float4 u0 = r0[k4];
                float4 u1 = r1[k4];
#pragma unroll
                for (int e = 0; e < EPW; e++) {
                    float4 av = reinterpret_cast<const float4*>(wa + e * 64)[k4];
                    b0[e] += av.x * u0.x + av.y * u0.y + av.z * u0.z + av.w * u0.w;
                    b1[e] += av.x * u1.x + av.y * u1.y + av.z * u1.z + av.w * u1.w;
                }
            }
        }
        __syncwarp();
#pragma unroll
        for (int e = 0; e < EPW; e++) {
            wa[e * 64 + lane] = silu(b0[e]);
            wa[e * 64 + 32 + lane] = silu(b1[e]);
        }
        __syncwarp();
        // -------- layer 3: [64] -> [128] (w1..w4 per-edge TP weights) --------
        float c0[EPW], c1[EPW], c2[EPW], c3[EPW];
#pragma unroll
        for (int e = 0; e < EPW; e++) { c0[e] = 0.f; c1[e] = 0.f; c2[e] = 0.f; c3[e] = 0.f; }
        {
            const float4* q0 = reinterpret_cast<const float4*>(sw2t + lane * PADW);
            const float4* q1 = reinterpret_cast<const float4*>(sw2t + (lane + 32) * PADW);
            const float4* q2 = reinterpret_cast<const float4*>(sw2t + (lane + 64) * PADW);
            const float4* q3 = reinterpret_cast<const float4*>(sw2t + (lane + 96) * PADW);
#pragma unroll
            for (int k4 = 0; k4 < 16; k4++) {
                float4 v0 = q0[k4], v1 = q1[k4], v2 = q2[k4], v3 = q3[k4];
#pragma unroll
                for (int e = 0; e < EPW; e++) {
                    float4 av = reinterpret_cast<const float4*>(wa + e * 64)[k4];
                    c0[e] += av.x * v0.x + av.y * v0.y + av.z * v0.z + av.w * v0.w;
                    c1[e] += av.x * v1.x + av.y * v1.y + av.z * v1.z + av.w * v1.w;
                    c2[e] += av.x * v2.x + av.y * v2.y + av.z * v2.z + av.w * v2.w;
                    c3[e] += av.x * v3.x + av.y * v3.y + av.z * v3.z + av.w * v3.w;
                }
            }
        }
        // -------- gather + CG tensor product + coalesced atomic scatter --------
#pragma unroll
        for (int e = 0; e < EPW; e++) {
            int eg = base + e;
            int s = __ldg(senders + eg);
            int r = __ldg(receivers + eg);
            float es = g_hsl[s * MULC + lane];
            float sh0 = g_sh1[eg * 3 + 0];
            float sh1v = g_sh1[eg * 3 + 1];
            float sh2 = g_sh1[eg * 3 + 2];
            atomicAdd(&g_n0[r * 64 + lane], c0[e] * es);           // 0e x 0e
            float w3es = c2[e] * es;                               // 0e x 1o
            atomicAdd(&g_n1[(r * 3 + 0) * 64 + lane], w3es * sh0);
            atomicAdd(&g_n1[(r * 3 + 1) * 64 + lane], w3es * sh1v);
            atomicAdd(&g_n1[(r * 3 + 2) * 64 + lane], w3es * sh2);
            if (HAS_VEC) {
                float ev0 = g_hvl[(s * 3 + 0) * MULC + lane];
                float ev1 = g_hvl[(s * 3 + 1) * MULC + lane];
                float ev2 = g_hvl[(s * 3 + 2) * MULC + lane];
                float dot = ev0 * sh0 + ev1 * sh1v + ev2 * sh2;
                atomicAdd(&g_n0[r * 64 + 32 + lane],
                          c1[e] * dot * 0.5773502691896258f);      // 1o x 1o -> 0e
                float w4 = c3[e];                                  // 1o x 0e
                atomicAdd(&g_n1[(r * 3 + 0) * 64 + 32 + lane], w4 * ev0);
                atomicAdd(&g_n1[(r * 3 + 1) * 64 + 32 + lane], w4 * ev1);
                atomicAdd(&g_n1[(r * 3 + 2) * 64 + 32 + lane], w4 * ev2);
            }
        }
    }
}

// ---------------- node update: lin2 + residual + gated nonlinearity ----------------
__global__ void k_node_update(const float* __restrict__ w_lin2_s,
                              const float* __restrict__ w_lin2_v, int l) {
    int w = (blockIdx.x * blockDim.x + threadIdx.x) >> 5;
    int lane = threadIdx.x & 31;
    if (w >= NN) return;
    int n = w;
    const float* W2s = w_lin2_s + l * 64 * 64;
    const float* W2v = w_lin2_v + l * 64 * 32;
    float s0 = 0.f, s1 = 0.f, v0 = 0.f, v1 = 0.f, v2 = 0.f;
#pragma unroll 4
    for (int j = 0; j < 64; j++) {
        float nj = g_n0[n * 64 + j];
        s0 += nj * W2s[j * 64 + lane];
        s1 += nj * W2s[j * 64 + 32 + lane];
        float wv = W2v[j * 32 + lane];
        v0 += g_n1[(n * 3 + 0) * 64 + j] * wv;
        v1 += g_n1[(n * 3 + 1) * 64 + j] * wv;
        v2 += g_n1[(n * 3 + 2) * 64 + j] * wv;
    }
    const float SC_ = 0.0078125f;  // 1/AVG_NEIGH * 1/sqrt(64) = 1/128
    float so0 = s0 * SC_ + g_res_s[n * 64 + lane];
    float so1 = s1 * SC_ + g_res_s[n * 64 + 32 + lane];
    float hs = silu(so0);
    float gate = silu(so1);
    g_hs[n * 32 + lane] = hs;
    g_hv[(n * 3 + 0) * 32 + lane] = (v0 * SC_ + g_res_v[(n * 3 + 0) * 32 + lane]) * gate;
    g_hv[(n * 3 + 1) * 32 + lane] = (v1 * SC_ + g_res_v[(n * 3 + 1) * 32 + lane]) * gate;
    g_hv[(n * 3 + 2) * 32 + lane] = (v2 * SC_ + g_res_v[(n * 3 + 2) * 32 + lane]) * gate;
}

// ---------------- scalar readout ----------------
__global__ void k_readout(const float* __restrict__ w_out1,
                          const float* __restrict__ w_out2,
                          float* __restrict__ out) {
    int w = (blockIdx.x * blockDim.x + threadIdx.x) >> 5;
    int lane = threadIdx.x & 31;
    if (w >= NN) return;
    int n = w;
    float z = 0.f;
    if (lane < 16) {
#pragma unroll 8
        for (int u = 0; u < 32; u++)
            z += g_hs[n * 32 + u] * w_out1[u * 16 + lane];
        z = z * 0.17677669529663687f * w_out2[lane];  // /sqrt(32), *w_out2
    }
    z += __shfl_xor_sync(0xffffffffu, z, 8);
    z += __shfl_xor_sync(0xffffffffu, z, 4);
    z += __shfl_xor_sync(0xffffffffu, z, 2);
    z += __shfl_xor_sync(0xffffffffu, z, 1);
    if (lane == 0) out[n] = z * 0.25f;  // /sqrt(16)
}

// ---------------- launch ----------------
extern "C" void kernel_launch(void* const* d_in, const int* in_sizes, int n_in,
                              void* d_out, int out_size) {
    const float* edge_vectors = (const float*)d_in[0];
    const int* species        = (const int*)d_in[1];
    const int* senders        = (const int*)d_in[2];
    const int* receivers      = (const int*)d_in[3];
    const float* embed_w      = (const float*)d_in[4];
    const float* w_res_s      = (const float*)d_in[5];
    const float* w_res_v      = (const float*)d_in[6];
    const float* w_lin1_s     = (const float*)d_in[7];
    const float* w_lin1_v     = (const float*)d_in[8];
    const float* mlp_w0       = (const float*)d_in[9];
    const float* mlp_w1       = (const float*)d_in[10];
    const float* mlp_w2       = (const float*)d_in[11];
    const float* w_lin2_s     = (const float*)d_in[12];
    const float* w_lin2_v     = (const float*)d_in[13];
    const float* w_out1       = (const float*)d_in[14];
    const float* w_out2       = (const float*)d_in[15];
    float* out = (float*)d_out;

    const size_t smem = SMEM_FLOATS * sizeof(float);  // ~62.5 KB -> needs opt-in
    cudaFuncSetAttribute(k_edge<false>, cudaFuncAttributeMaxDynamicSharedMemorySize, (int)smem);
    cudaFuncSetAttribute(k_edge<true>, cudaFuncAttributeMaxDynamicSharedMemorySize, (int)smem);

    k_edge_pre<<<(EE + 255) / 256, 256>>>(edge_vectors);
    k_node_init<<<(NN * MULC + 255) / 256, 256>>>(species, embed_w);

    const int NPB = (NN + 7) / 8;  // warp-per-node kernels, 8 warps/block
    const int EG = 1776;           // edge kernel grid (clean waves at occ 2 or 3)

    // layer 0: h_v == 0 -> vector paths vanish
    k_node_prep<false><<<NPB, 256>>>(species, w_res_s, w_res_v, w_lin1_s, w_lin1_v, 0);
    k_edge<false><<<EG, 256, smem>>>(mlp_w0, mlp_w1, mlp_w2, senders, receivers, 0);
    k_node_update<<<NPB, 256>>>(w_lin2_s, w_lin2_v, 0);

    // layer 1: full path
    k_node_prep<true><<<NPB, 256>>>(species, w_res_s, w_res_v, w_lin1_s, w_lin1_v, 1);
    k_edge<true><<<EG, 256, smem>>>(mlp_w0, mlp_w1, mlp_w2, senders, receivers, 1);
    k_node_update<<<NPB, 256>>>(w_lin2_s, w_lin2_v, 1);

    k_readout<<<NPB, 256>>>(w_out1, w_out2, out);
}

// round 2
// speedup vs baseline: 2.8556x; 2.8556x over previous
#include <cuda_runtime.h>

#define NN 50000
#define EE 800000
#define MULC 32
#define SC 5
#define NBC 8
#define HC 64
#define NWC 128
#define TBINS 4096
#define RMAXF 5.0f

// ---------------- device scratch (static, no allocation) ----------------
__device__ float g_sh1[EE * 3];          // l=1 SH per edge
__device__ float g_p[EE];                // table position in [0,TBINS-1], or -1 => skip (r>=RMAX)
__device__ float g_hs[NN * MULC];        // node scalar feats
__device__ float g_hv[NN * 3 * MULC];    // node vector feats, [n][i][u]
__device__ float g_hsl[NN * MULC];       // lin1 scalar
__device__ float g_hvl[NN * 3 * MULC];   // lin1 vector, [n][i][u]
__device__ float g_res_s[NN * 2 * MULC];
__device__ float g_res_v[NN * 3 * MULC]; // [n][i][u]
__device__ float g_n0[NN * 2 * MULC];    // scatter accum scalars
__device__ float g_n1[NN * 3 * 2 * MULC];// scatter accum vectors, [n][i][c] c<64
__device__ float g_tab0[TBINS * 64];     // layer0 LUT: [bin][u][2] = (w1[u], w3[u])
__device__ float g_tab1[TBINS * 128];    // layer1 LUT: [bin][u][4] = (w1,w2,w3,w4)[u]

__device__ __forceinline__ float silu(float x) {
    return x / (1.0f + __expf(-x));
}

// ---------------- edge precompute: sh1 + table position ----------------
__global__ void k_edge_pre(const float* __restrict__ evec) {
    int e = blockIdx.x * blockDim.x + threadIdx.x;
    if (e >= EE) return;
    float x = evec[e * 3 + 0], y = evec[e * 3 + 1], z = evec[e * 3 + 2];
    float r = sqrtf(x * x + y * y + z * z + 1e-12f);
    float ir = 1.0f / r;
    const float SQ3 = 1.7320508075688772f;
    g_sh1[e * 3 + 0] = SQ3 * x * ir;
    g_sh1[e * 3 + 1] = SQ3 * y * ir;
    g_sh1[e * 3 + 2] = SQ3 * z * ir;
    // envelope (and hence the bias-free radial MLP) is exactly 0 for r >= RMAX
    g_p[e] = (r < RMAXF) ? r * ((float)(TBINS - 1) / RMAXF) : -1.0f;
}

// ---------------- build radial-MLP lookup table ----------------
// one block (128 thr) per bin; evaluates the exact MLP at r = bin*RMAX/(TBINS-1)
__global__ void k_build_table(const float* __restrict__ mlp_w0,
                              const float* __restrict__ mlp_w1,
                              const float* __restrict__ mlp_w2, int l) {
    __shared__ float a1[HC];
    __shared__ float a2[HC];
    __shared__ float eemb[NBC];
    int bin = blockIdx.x;
    int tid = threadIdx.x;
    const float* w0 = mlp_w0 + l * NBC * HC;
    const float* w1 = mlp_w1 + l * HC * HC;
    const float* w2 = mlp_w2 + l * HC * NWC;
    if (tid < NBC) {
        float r = (float)bin * (RMAXF / (float)(TBINS - 1));
        float rs = fmaxf(r, 1e-6f);
        float ir = 1.0f / rs;
        float xr = rs * (1.0f / RMAXF);
        float x3 = xr * xr * xr, x6 = x3 * x3, x7 = x6 * xr, x8 = x7 * xr;
        float env = 1.0f - 28.0f * x6 + 48.0f * x7 - 21.0f * x8;
        const float PI_ = 3.14159265358979323846f;
        eemb[tid] = 0.6324555320336759f * ir * env * sinf(PI_ * xr * (float)(tid + 1));
    }
    __syncthreads();
    if (tid < HC) {
        float acc = 0.f;
#pragma unroll
        for (int k = 0; k < NBC; k++) acc += eemb[k] * w0[k * HC + tid];
        a1[tid] = silu(acc * 0.35355339059327373f);  // 1/sqrt(8)
    }
    __syncthreads();
    if (tid < HC) {
        float acc = 0.f;
#pragma unroll 8
        for (int k = 0; k < HC; k++) acc += a1[k] * w1[k * HC + tid];
        a2[tid] = silu(acc * 0.125f);                // 1/sqrt(64)
    }
    __syncthreads();
    {
        float acc = 0.f;
#pragma unroll 8
        for (int k = 0; k < HC; k++) acc += a2[k] * w2[k * NWC + tid];
        int u = tid & 31, path = tid >> 5;           // path 0..3 = w1..w4
        if (l == 0) {
            if (path == 0) g_tab0[bin * 64 + u * 2 + 0] = acc;       // w1
            else if (path == 2) g_tab0[bin * 64 + u * 2 + 1] = acc;  // w3
        } else {
            g_tab1[bin * 128 + u * 4 + path] = acc;
        }
    }
}

// ---------------- node embedding ----------------
__global__ void k_node_init(const int* __restrict__ species,
                            const float* __restrict__ embed_w) {
    int idx = blockIdx.x * blockDim.x + threadIdx.x;
    if (idx >= NN * MULC) return;
    int n = idx >> 5, u = idx & 31;
    g_hs[idx] = embed_w[species[n] * MULC + u] * 0.4472135954999579f; // /sqrt(5)
}

// ---------------- per-layer node prep: residual TP + lin1 + zero accums ----------------
template <bool HAS_VEC>
__global__ void k_node_prep(const int* __restrict__ species,
                            const float* __restrict__ w_res_s,
                            const float* __restrict__ w_res_v,
                            const float* __restrict__ w_lin1_s,
                            const float* __restrict__ w_lin1_v, int l) {
    int w = (blockIdx.x * blockDim.x + threadIdx.x) >> 5;
    int lane = threadIdx.x & 31;
    if (w >= NN) return;
    int n = w;
    int spec = species[n];
    const float* Wl1s = w_lin1_s + l * MULC * MULC;
    const float* Wl1v = w_lin1_v + l * MULC * MULC;
    const float* Wrs = w_res_s + l * MULC * SC * 2 * MULC + spec * 2 * MULC;
    const float* Wrv = w_res_v + l * MULC * SC * MULC + spec * MULC;
    float a_hs = 0.f, a_rs0 = 0.f, a_rs1 = 0.f;
    float a_hv0 = 0.f, a_hv1 = 0.f, a_hv2 = 0.f;
    float a_rv0 = 0.f, a_rv1 = 0.f, a_rv2 = 0.f;
#pragma unroll 4
    for (int u = 0; u < MULC; u++) {
        float hsu = g_hs[n * MULC + u];
        a_hs  += hsu * Wl1s[u * MULC + lane];
        a_rs0 += hsu * Wrs[u * SC * 2 * MULC + lane];
        a_rs1 += hsu * Wrs[u * SC * 2 * MULC + MULC + lane];
        if (HAS_VEC) {
            float wv = Wl1v[u * MULC + lane];
            float wr = Wrv[u * SC * MULC + lane];
            float h0 = g_hv[(n * 3 + 0) * MULC + u];
            float h1 = g_hv[(n * 3 + 1) * MULC + u];
            float h2 = g_hv[(n * 3 + 2) * MULC + u];
            a_hv0 += h0 * wv; a_hv1 += h1 * wv; a_hv2 += h2 * wv;
            a_rv0 += h0 * wr; a_rv1 += h1 * wr; a_rv2 += h2 * wr;
        }
    }
    const float IS32 = 0.17677669529663687f;   // 1/sqrt(32)
    const float IS160 = 0.07905694150420949f;  // 1/sqrt(160)
    g_hsl[n * MULC + lane] = a_hs * IS32;
    g_res_s[n * 2 * MULC + lane] = a_rs0 * IS160;
    g_res_s[n * 2 * MULC + MULC + lane] = a_rs1 * IS160;
    g_hvl[(n * 3 + 0) * MULC + lane] = a_hv0 * IS32;
    g_hvl[(n * 3 + 1) * MULC + lane] = a_hv1 * IS32;
    g_hvl[(n * 3 + 2) * MULC + lane] = a_hv2 * IS32;
    g_res_v[(n * 3 + 0) * MULC + lane] = a_rv0 * IS160;
    g_res_v[(n * 3 + 1) * MULC + lane] = a_rv1 * IS160;
    g_res_v[(n * 3 + 2) * MULC + lane] = a_rv2 * IS160;
    g_n0[n * 64 + lane] = 0.f;
    g_n0[n * 64 + 32 + lane] = 0.f;
#pragma unroll
    for (int i = 0; i < 3; i++) {
        g_n1[(n * 3 + i) * 64 + lane] = 0.f;
        g_n1[(n * 3 + i) * 64 + 32 + lane] = 0.f;
    }
}

// ---------------- main edge kernel: LUT-interp TP weights + CG product + scatter ----------------
template <bool HAS_VEC>
__global__ void __launch_bounds__(256) k_edge(const int* __restrict__ senders,
                                              const int* __restrict__ receivers) {
    int gw = (blockIdx.x * blockDim.x + threadIdx.x) >> 5;
    int lane = threadIdx.x & 31;
    int nw = (gridDim.x * blockDim.x) >> 5;
    for (int e = gw; e < EE; e += nw) {
        float p = g_p[e];
        if (p < 0.0f) continue;                 // r >= RMAX: MLP output identically 0
        int i = (int)p;
        if (i > TBINS - 2) i = TBINS - 2;
        float f = p - (float)i;
        int s = __ldg(senders + e);
        int r = __ldg(receivers + e);
        float sh0 = g_sh1[e * 3 + 0];
        float sh1v = g_sh1[e * 3 + 1];
        float sh2 = g_sh1[e * 3 + 2];
        float es = g_hsl[s * MULC + lane];
        if (!HAS_VEC) {
            float2 a = *reinterpret_cast<const float2*>(g_tab0 + i * 64 + lane * 2);
            float2 b = *reinterpret_cast<const float2*>(g_tab0 + (i + 1) * 64 + lane * 2);
            float w1 = fmaf(f, b.x - a.x, a.x);
            float w3 = fmaf(f, b.y - a.y, a.y);
            atomicAdd(&g_n0[r * 64 + lane], w1 * es);
            float w3es = w3 * es;
            atomicAdd(&g_n1[(r * 3 + 0) * 64 + lane], w3es * sh0);
            atomicAdd(&g_n1[(r * 3 + 1) * 64 + lane], w3es * sh1v);
            atomicAdd(&g_n1[(r * 3 + 2) * 64 + lane], w3es * sh2);
        } else {
            float4 a = *reinterpret_cast<const float4*>(g_tab1 + i * 128 + lane * 4);
            float4 b = *reinterpret_cast<const float4*>(g_tab1 + (i + 1) * 128 + lane * 4);
            float w1 = fmaf(f, b.x - a.x, a.x);
            float w2 = fmaf(f, b.y - a.y, a.y);
            float w3 = fmaf(f, b.z - a.z, a.z);
            float w4 = fmaf(f, b.w - a.w, a.w);
            float ev0 = g_hvl[(s * 3 + 0) * MULC + lane];
            float ev1 = g_hvl[(s * 3 + 1) * MULC + lane];
            float ev2 = g_hvl[(s * 3 + 2) * MULC + lane];
            atomicAdd(&g_n0[r * 64 + lane], w1 * es);
            float dot = ev0 * sh0 + ev1 * sh1v + ev2 * sh2;
            atomicAdd(&g_n0[r * 64 + 32 + lane], w2 * dot * 0.5773502691896258f);
            float w3es = w3 * es;
            atomicAdd(&g_n1[(r * 3 + 0) * 64 + lane], w3es * sh0);
            atomicAdd(&g_n1[(r * 3 + 1) * 64 + lane], w3es * sh1v);
            atomicAdd(&g_n1[(r * 3 + 2) * 64 + lane], w3es * sh2);
            atomicAdd(&g_n1[(r * 3 + 0) * 64 + 32 + lane], w4 * ev0);
            atomicAdd(&g_n1[(r * 3 + 1) * 64 + 32 + lane], w4 * ev1);
            atomicAdd(&g_n1[(r * 3 + 2) * 64 + 32 + lane], w4 * ev2);
        }
    }
}

// ---------------- node update: lin2 + residual + gated nonlinearity (+ fused readout) ----------------
template <bool READOUT>
__global__ void k_node_update(const float* __restrict__ w_lin2_s,
                              const float* __restrict__ w_lin2_v,
                              const float* __restrict__ w_out1,
                              const float* __restrict__ w_out2,
                              float* __restrict__ out, int l) {
    int w = (blockIdx.x * blockDim.x + threadIdx.x) >> 5;
    int lane = threadIdx.x & 31;
    if (w >= NN) return;
    int n = w;
    const float* W2s = w_lin2_s + l * 64 * 64;
    const float* W2v = w_lin2_v + l * 64 * 32;
    float s0 = 0.f, s1 = 0.f, v0 = 0.f, v1 = 0.f, v2 = 0.f;
#pragma unroll 4
    for (int j = 0; j < 64; j++) {
        float nj = g_n0[n * 64 + j];
        s0 += nj * W2s[j * 64 + lane];
        s1 += nj * W2s[j * 64 + 32 + lane];
        float wv = W2v[j * 32 + lane];
        v0 += g_n1[(n * 3 + 0) * 64 + j] * wv;
        v1 += g_n1[(n * 3 + 1) * 64 + j] * wv;
        v2 += g_n1[(n * 3 + 2) * 64 + j] * wv;
    }
    const float SC_ = 0.0078125f;  // 1/16 * 1/sqrt(64)
    float so0 = s0 * SC_ + g_res_s[n * 64 + lane];
    float so1 = s1 * SC_ + g_res_s[n * 64 + 32 + lane];
    float hs = silu(so0);
    float gate = silu(so1);
    if (!READOUT) {
        g_hs[n * 32 + lane] = hs;
        g_hv[(n * 3 + 0) * 32 + lane] = (v0 * SC_ + g_res_v[(n * 3 + 0) * 32 + lane]) * gate;
        g_hv[(n * 3 + 1) * 32 + lane] = (v1 * SC_ + g_res_v[(n * 3 + 1) * 32 + lane]) * gate;
        g_hv[(n * 3 + 2) * 32 + lane] = (v2 * SC_ + g_res_v[(n * 3 + 2) * 32 + lane]) * gate;
    } else {
        // readout is linear@linear: e = h_s . (w_out1 @ w_out2) / sqrt(32*16)
        float wc = 0.f;
#pragma unroll
        for (int k = 0; k < 16; k++) wc += w_out1[lane * 16 + k] * w_out2[k];
        float z = hs * wc;
        z += __shfl_xor_sync(0xffffffffu, z, 16);
        z += __shfl_xor_sync(0xffffffffu, z, 8);
        z += __shfl_xor_sync(0xffffffffu, z, 4);
        z += __shfl_xor_sync(0xffffffffu, z, 2);
        z += __shfl_xor_sync(0xffffffffu, z, 1);
        if (lane == 0) out[n] = z * (0.17677669529663687f * 0.25f);
    }
}

// ---------------- launch ----------------
extern "C" void kernel_launch(void* const* d_in, const int* in_sizes, int n_in,
                              void* d_out, int out_size) {
    const float* edge_vectors = (const float*)d_in[0];
    const int* species        = (const int*)d_in[1];
    const int* senders        = (const int*)d_in[2];
    const int* receivers      = (const int*)d_in[3];
    const float* embed_w      = (const float*)d_in[4];
    const float* w_res_s      = (const float*)d_in[5];
    const float* w_res_v      = (const float*)d_in[6];
    const float* w_lin1_s     = (const float*)d_in[7];
    const float* w_lin1_v     = (const float*)d_in[8];
    const float* mlp_w0       = (const float*)d_in[9];
    const float* mlp_w1       = (const float*)d_in[10];
    const float* mlp_w2       = (const float*)d_in[11];
    const float* w_lin2_s     = (const float*)d_in[12];
    const float* w_lin2_v     = (const float*)d_in[13];
    const float* w_out1       = (const float*)d_in[14];
    const float* w_out2       = (const float*)d_in[15];
    float* out = (float*)d_out;

    k_edge_pre<<<(EE + 255) / 256, 256>>>(edge_vectors);
    k_build_table<<<TBINS, 128>>>(mlp_w0, mlp_w1, mlp_w2, 0);
    k_build_table<<<TBINS, 128>>>(mlp_w0, mlp_w1, mlp_w2, 1);
    k_node_init<<<(NN * MULC + 255) / 256, 256>>>(species, embed_w);

    const int NPB = (NN + 7) / 8;  // warp-per-node kernels, 8 warps/block
    const int EG = 2048;           // edge kernel grid

    // layer 0: h_v == 0 -> vector paths vanish
    k_node_prep<false><<<NPB, 256>>>(species, w_res_s, w_res_v, w_lin1_s, w_lin1_v, 0);
    k_edge<false><<<EG, 256>>>(senders, receivers);
    k_node_update<false><<<NPB, 256>>>(w_lin2_s, w_lin2_v, w_out1, w_out2, out, 0);

    // layer 1: full path
    k_node_prep<true><<<NPB, 256>>>(species, w_res_s, w_res_v, w_lin1_s, w_lin1_v, 1);
    k_edge<true><<<EG, 256>>>(senders, receivers);
    k_node_update<true><<<NPB, 256>>>(w_lin2_s, w_lin2_v, w_out1, w_out2, out, 1);
}

// round 3
// speedup vs baseline: 3.2357x; 1.1331x over previous
#include <cuda_runtime.h>

#define NN 50000
#define EE 800000
#define MULC 32
#define SC 5
#define NBC 8
#define HC 64
#define NWC 128
#define TBINS 2048
#define RMAXF 5.0f

// ---------------- device scratch ----------------
__device__ float g_hs[NN * 32];
__device__ float g_hv[NN * 3 * 32];
__device__ float g_hsl[NN * 32];
__device__ float g_hvl[NN * 3 * 32];
__device__ float g_res_s[NN * 64];
__device__ float g_res_v[NN * 3 * 32];
__device__ float g_n0[NN * 64];
__device__ float g_n1[NN * 3 * 64];
__device__ float g_tab0[TBINS * 64];
__device__ float g_tab1[TBINS * 128];
__device__ int g_cnt[NN];        // degree, then cursor
__device__ int g_off[NN + 1];
__device__ float4 g_epack[EE];   // CSR-ordered (p, sh0, sh1, sh2)
__device__ int g_esend[EE];      // CSR-ordered sender id
__device__ int g_nsort[NN];      // species-sorted node ids
__device__ int g_scnt[SC];
__device__ int g_scur[SC];

__device__ __forceinline__ float silu(float x) { return x / (1.0f + __expf(-x)); }

// ---------------- CSR build ----------------
__global__ void k_zero() {
    int t = blockIdx.x * blockDim.x + threadIdx.x;
    if (t < NN) g_cnt[t] = 0;
    if (t < SC) g_scnt[t] = 0;
}

__global__ void k_hist(const float* __restrict__ evec, const int* __restrict__ recv) {
    int e = blockIdx.x * blockDim.x + threadIdx.x;
    if (e >= EE) return;
    float x = evec[e * 3], y = evec[e * 3 + 1], z = evec[e * 3 + 2];
    float r2 = x * x + y * y + z * z;
    if (r2 < RMAXF * RMAXF) atomicAdd(&g_cnt[recv[e]], 1);
}

__global__ void k_spec_hist(const int* __restrict__ species) {
    int t = blockIdx.x * blockDim.x + threadIdx.x;
    if (t < NN) atomicAdd(&g_scnt[species[t]], 1);
}

__global__ void k_scan() {
    __shared__ int wsum[32];
    __shared__ int stot;
    int t = threadIdx.x, lane = t & 31, wid = t >> 5;
    int carry = 0;
    for (int base = 0; base < NN; base += 1024) {
        int idx = base + t;
        int v = (idx < NN) ? g_cnt[idx] : 0;
        int x = v;
#pragma unroll
        for (int d = 1; d < 32; d <<= 1) {
            int y = __shfl_up_sync(0xffffffffu, x, d);
            if (lane >= d) x += y;
        }
        if (lane == 31) wsum[wid] = x;
        __syncthreads();
        if (wid == 0) {
            int s = wsum[lane];
#pragma unroll
            for (int d = 1; d < 32; d <<= 1) {
                int y = __shfl_up_sync(0xffffffffu, s, d);
                if (lane >= d) s += y;
            }
            wsum[lane] = s;
            if (lane == 31) stot = s;
        }
        __syncthreads();
        int incl = x + (wid > 0 ? wsum[wid - 1] : 0);
        int excl = carry + incl - v;
        if (idx < NN) { g_off[idx] = excl; g_cnt[idx] = excl; }
        carry += stot;
        __syncthreads();
    }
    if (t == 0) {
        g_off[NN] = carry;
        int acc = 0;
        for (int s = 0; s < SC; s++) { int c = g_scnt[s]; g_scnt[s] = acc; g_scur[s] = acc; acc += c; }
    }
}

__global__ void k_spec_scatter(const int* __restrict__ species) {
    int t = blockIdx.x * blockDim.x + threadIdx.x;
    if (t >= NN) return;
    int pos = atomicAdd(&g_scur[species[t]], 1);
    g_nsort[pos] = t;
}

__global__ void k_scatter(const float* __restrict__ evec, const int* __restrict__ senders,
                          const int* __restrict__ recv) {
    int e = blockIdx.x * blockDim.x + threadIdx.x;
    if (e >= EE) return;
    float x = evec[e * 3], y = evec[e * 3 + 1], z = evec[e * 3 + 2];
    float r2 = x * x + y * y + z * z;
    if (r2 >= RMAXF * RMAXF) return;
    float r = sqrtf(r2 + 1e-12f);
    float ir = 1.0f / r;
    const float SQ3 = 1.7320508075688772f;
    float p = r * ((float)(TBINS - 1) / RMAXF);
    int pos = atomicAdd(&g_cnt[recv[e]], 1);
    g_epack[pos] = make_float4(p, SQ3 * x * ir, SQ3 * y * ir, SQ3 * z * ir);
    g_esend[pos] = senders[e];
}

// ---------------- radial-MLP lookup table ----------------
__global__ void k_build_table(const float* __restrict__ mlp_w0,
                              const float* __restrict__ mlp_w1,
                              const float* __restrict__ mlp_w2, int l) {
    __shared__ float a1[HC];
    __shared__ float a2[HC];
    __shared__ float eemb[NBC];
    int bin = blockIdx.x;
    int tid = threadIdx.x;
    const float* w0 = mlp_w0 + l * NBC * HC;
    const float* w1 = mlp_w1 + l * HC * HC;
    const float* w2 = mlp_w2 + l * HC * NWC;
    if (tid < NBC) {
        float r = (float)bin * (RMAXF / (float)(TBINS - 1));
        float rs = fmaxf(r, 1e-6f);
        float ir = 1.0f / rs;
        float xr = rs * (1.0f / RMAXF);
        float x3 = xr * xr * xr, x6 = x3 * x3, x7 = x6 * xr, x8 = x7 * xr;
        float env = 1.0f - 28.0f * x6 + 48.0f * x7 - 21.0f * x8;
        const float PI_ = 3.14159265358979323846f;
        eemb[tid] = 0.6324555320336759f * ir * env * sinf(PI_ * xr * (float)(tid + 1));
    }
    __syncthreads();
    if (tid < HC) {
        float acc = 0.f;
#pragma unroll
        for (int k = 0; k < NBC; k++) acc += eemb[k] * w0[k * HC + tid];
        a1[tid] = silu(acc * 0.35355339059327373f);
    }
    __syncthreads();
    if (tid < HC) {
        float acc = 0.f;
#pragma unroll 8
        for (int k = 0; k < HC; k++) acc += a1[k] * w1[k * HC + tid];
        a2[tid] = silu(acc * 0.125f);
    }
    __syncthreads();
    {
        float acc = 0.f;
#pragma unroll 8
        for (int k = 0; k < HC; k++) acc += a2[k] * w2[k * NWC + tid];
        int u = tid & 31, path = tid >> 5;
        if (l == 0) {
            if (path == 0) g_tab0[bin * 64 + u * 2 + 0] = acc;
            else if (path == 2) g_tab0[bin * 64 + u * 2 + 1] = acc;
        } else {
            g_tab1[bin * 128 + u * 4 + path] = acc;
        }
    }
}

// ---------------- node embedding ----------------
__global__ void k_node_init(const int* __restrict__ species, const float* __restrict__ embed_w) {
    int idx = blockIdx.x * blockDim.x + threadIdx.x;
    if (idx >= NN * 32) return;
    int n = idx >> 5, u = idx & 31;
    g_hs[idx] = embed_w[species[n] * 32 + u] * 0.4472135954999579f;
}

// ---------------- node prep: lin1 + residual (4 nodes per warp, species-sorted) ----------------
template <bool HAS_VEC>
__global__ void __launch_bounds__(256) k_node_prep(const int* __restrict__ species,
                                                   const float* __restrict__ w_res_s,
                                                   const float* __restrict__ w_res_v,
                                                   const float* __restrict__ w_lin1_s,
                                                   const float* __restrict__ w_lin1_v, int l) {
    int w = (blockIdx.x * blockDim.x + threadIdx.x) >> 5;
    int lane = threadIdx.x & 31;
    int base = w * 4;
    if (base >= NN) return;
    int nid[4], sp[4];
#pragma unroll
    for (int g = 0; g < 4; g++) { nid[g] = g_nsort[base + g]; sp[g] = species[nid[g]]; }
    bool uni = (sp[0] == sp[1]) && (sp[1] == sp[2]) && (sp[2] == sp[3]);
    const float* Wl1s = w_lin1_s + l * 1024;
    const float* Wl1v = w_lin1_v + l * 1024;
    float a_hs[4] = {0, 0, 0, 0}, a_rs0[4] = {0, 0, 0, 0}, a_rs1[4] = {0, 0, 0, 0};
    float a_hv[4][3] = {{0}}, a_rv[4][3] = {{0}};
#pragma unroll 2
    for (int uc = 0; uc < 8; uc++) {
        int u0 = uc * 4;
        float ws[4], wv[4], wr0[4], wr1[4], wrv[4];
#pragma unroll
        for (int d = 0; d < 4; d++) {
            ws[d] = Wl1s[(u0 + d) * 32 + lane];
            if (HAS_VEC) wv[d] = Wl1v[(u0 + d) * 32 + lane];
        }
        if (uni) {
#pragma unroll
            for (int d = 0; d < 4; d++) {
                const float* rs = w_res_s + ((size_t)((l * 32 + u0 + d) * SC + sp[0])) * 64;
                wr0[d] = rs[lane];
                wr1[d] = rs[32 + lane];
                if (HAS_VEC) wrv[d] = w_res_v[((size_t)((l * 32 + u0 + d) * SC + sp[0])) * 32 + lane];
            }
        }
#pragma unroll
        for (int g = 0; g < 4; g++) {
            float r0[4], r1[4], rv[4];
            if (uni) {
#pragma unroll
                for (int d = 0; d < 4; d++) { r0[d] = wr0[d]; r1[d] = wr1[d]; if (HAS_VEC) rv[d] = wrv[d]; }
            } else {
#pragma unroll
                for (int d = 0; d < 4; d++) {
                    const float* rs = w_res_s + ((size_t)((l * 32 + u0 + d) * SC + sp[g])) * 64;
                    r0[d] = rs[lane];
                    r1[d] = rs[32 + lane];
                    if (HAS_VEC) rv[d] = w_res_v[((size_t)((l * 32 + u0 + d) * SC + sp[g])) * 32 + lane];
                }
            }
            float4 xs = *reinterpret_cast<const float4*>(&g_hs[nid[g] * 32 + u0]);
            float xa[4] = {xs.x, xs.y, xs.z, xs.w};
#pragma unroll
            for (int d = 0; d < 4; d++) {
                a_hs[g] += xa[d] * ws[d];
                a_rs0[g] += xa[d] * r0[d];
                a_rs1[g] += xa[d] * r1[d];
            }
            if (HAS_VEC) {
#pragma unroll
                for (int i = 0; i < 3; i++) {
                    float4 xv = *reinterpret_cast<const float4*>(&g_hv[(nid[g] * 3 + i) * 32 + u0]);
                    float xb[4] = {xv.x, xv.y, xv.z, xv.w};
#pragma unroll
                    for (int d = 0; d < 4; d++) {
                        a_hv[g][i] += xb[d] * wv[d];
                        a_rv[g][i] += xb[d] * rv[d];
                    }
                }
            }
        }
    }
    const float IS32 = 0.17677669529663687f;   // 1/sqrt(32)
    const float IS160 = 0.07905694150420949f;  // 1/sqrt(160)
#pragma unroll
    for (int g = 0; g < 4; g++) {
        int n = nid[g];
        g_hsl[n * 32 + lane] = a_hs[g] * IS32;
        g_res_s[n * 64 + lane] = a_rs0[g] * IS160;
        g_res_s[n * 64 + 32 + lane] = a_rs1[g] * IS160;
#pragma unroll
        for (int i = 0; i < 3; i++) {
            if (HAS_VEC) {
                g_hvl[(n * 3 + i) * 32 + lane] = a_hv[g][i] * IS32;
                g_res_v[(n * 3 + i) * 32 + lane] = a_rv[g][i] * IS160;
            } else {
                g_res_v[(n * 3 + i) * 32 + lane] = 0.f;
            }
        }
    }
}

// ---------------- edge gather: LUT-interp TP + register accumulation (warp per node) ----------------
template <bool HAS_VEC>
__global__ void __launch_bounds__(256) k_gather() {
    int n = (blockIdx.x * blockDim.x + threadIdx.x) >> 5;
    int lane = threadIdx.x & 31;
    if (n >= NN) return;
    int e = g_off[n], end = g_off[n + 1];
    float a0 = 0.f, a1 = 0.f;
    float c3x = 0.f, c3y = 0.f, c3z = 0.f, c4x = 0.f, c4y = 0.f, c4z = 0.f;
    for (; e < end; e++) {
        float4 pk = __ldg(&g_epack[e]);
        int s = __ldg(&g_esend[e]);
        int i = min((int)pk.x, TBINS - 2);
        float f = pk.x - (float)i;
        float es = g_hsl[s * 32 + lane];
        if (!HAS_VEC) {
            float2 ta = *reinterpret_cast<const float2*>(&g_tab0[i * 64 + lane * 2]);
            float2 tb = *reinterpret_cast<const float2*>(&g_tab0[(i + 1) * 64 + lane * 2]);
            float w1 = fmaf(f, tb.x - ta.x, ta.x);
            float w3 = fmaf(f, tb.y - ta.y, ta.y);
            a0 += w1 * es;
            float w3es = w3 * es;
            c3x += w3es * pk.y; c3y += w3es * pk.z; c3z += w3es * pk.w;
        } else {
            float4 ta = *reinterpret_cast<const float4*>(&g_tab1[i * 128 + lane * 4]);
            float4 tb = *reinterpret_cast<const float4*>(&g_tab1[(i + 1) * 128 + lane * 4]);
            float w1 = fmaf(f, tb.x - ta.x, ta.x);
            float w2 = fmaf(f, tb.y - ta.y, ta.y);
            float w3 = fmaf(f, tb.z - ta.z, ta.z);
            float w4 = fmaf(f, tb.w - ta.w, ta.w);
            float ev0 = g_hvl[(s * 3 + 0) * 32 + lane];
            float ev1 = g_hvl[(s * 3 + 1) * 32 + lane];
            float ev2 = g_hvl[(s * 3 + 2) * 32 + lane];
            a0 += w1 * es;
            float dot = ev0 * pk.y + ev1 * pk.z + ev2 * pk.w;
            a1 += w2 * dot * 0.5773502691896258f;
            float w3es = w3 * es;
            c3x += w3es * pk.y; c3y += w3es * pk.z; c3z += w3es * pk.w;
            c4x += w4 * ev0; c4y += w4 * ev1; c4z += w4 * ev2;
        }
    }
    g_n0[n * 64 + lane] = a0;
    g_n0[n * 64 + 32 + lane] = a1;
    g_n1[(n * 3 + 0) * 64 + lane] = c3x; g_n1[(n * 3 + 0) * 64 + 32 + lane] = c4x;
    g_n1[(n * 3 + 1) * 64 + lane] = c3y; g_n1[(n * 3 + 1) * 64 + 32 + lane] = c4y;
    g_n1[(n * 3 + 2) * 64 + lane] = c3z; g_n1[(n * 3 + 2) * 64 + 32 + lane] = c4z;
}

// ---------------- node update: lin2 + residual + gate (4 nodes per warp, fused readout) ----------------
template <bool READOUT>
__global__ void __launch_bounds__(256) k_node_update(const float* __restrict__ w_lin2_s,
                                                     const float* __restrict__ w_lin2_v,
                                                     const float* __restrict__ w_out1,
                                                     const float* __restrict__ w_out2,
                                                     float* __restrict__ out, int l) {
    int w = (blockIdx.x * blockDim.x + threadIdx.x) >> 5;
    int lane = threadIdx.x & 31;
    int base = w * 4;
    if (base >= NN) return;
    const float* W2s = w_lin2_s + l * 4096;
    const float* W2v = w_lin2_v + l * 2048;
    float s0[4] = {0, 0, 0, 0}, s1[4] = {0, 0, 0, 0};
    float vv[4][3] = {{0}};
#pragma unroll 2
    for (int jc = 0; jc < 16; jc++) {
        int j0 = jc * 4;
        float wa[4], wb[4], wc[4];
#pragma unroll
        for (int d = 0; d < 4; d++) {
            wa[d] = W2s[(j0 + d) * 64 + lane];
            wb[d] = W2s[(j0 + d) * 64 + 32 + lane];
            wc[d] = W2v[(j0 + d) * 32 + lane];
        }
#pragma unroll
        for (int g = 0; g < 4; g++) {
            int n = base + g;
            float4 x = *reinterpret_cast<const float4*>(&g_n0[n * 64 + j0]);
            s0[g] += x.x * wa[0] + x.y * wa[1] + x.z * wa[2] + x.w * wa[3];
            s1[g] += x.x * wb[0] + x.y * wb[1] + x.z * wb[2] + x.w * wb[3];
#pragma unroll
            for (int i = 0; i < 3; i++) {
                float4 xv = *reinterpret_cast<const float4*>(&g_n1[(n * 3 + i) * 64 + j0]);
                vv[g][i] += xv.x * wc[0] + xv.y * wc[1] + xv.z * wc[2] + xv.w * wc[3];
            }
        }
    }
    float wcomb = 0.f;
    if (READOUT) {
#pragma unroll
        for (int k = 0; k < 16; k++) wcomb += w_out1[lane * 16 + k] * w_out2[k];
    }
    const float SC_ = 0.0078125f;  // 1/16 * 1/sqrt(64)
#pragma unroll
    for (int g = 0; g < 4; g++) {
        int n = base + g;
        float so0 = s0[g] * SC_ + g_res_s[n * 64 + lane];
        float so1 = s1[g] * SC_ + g_res_s[n * 64 + 32 + lane];
        float hs = silu(so0);
        float gate = silu(so1);
        if (!READOUT) {
            g_hs[n * 32 + lane] = hs;
#pragma unroll
            for (int i = 0; i < 3; i++)
                g_hv[(n * 3 + i) * 32 + lane] =
                    (vv[g][i] * SC_ + g_res_v[(n * 3 + i) * 32 + lane]) * gate;
        } else {
            float z = hs * wcomb;
            z += __shfl_xor_sync(0xffffffffu, z, 16);
            z += __shfl_xor_sync(0xffffffffu, z, 8);
            z += __shfl_xor_sync(0xffffffffu, z, 4);
            z += __shfl_xor_sync(0xffffffffu, z, 2);
            z += __shfl_xor_sync(0xffffffffu, z, 1);
            if (lane == 0) out[n] = z * (0.17677669529663687f * 0.25f);
        }
    }
}

// ---------------- launch ----------------
extern "C" void kernel_launch(void* const* d_in, const int* in_sizes, int n_in,
                              void* d_out, int out_size) {
    const float* edge_vectors = (const float*)d_in[0];
    const int* species        = (const int*)d_in[1];
    const int* senders        = (const int*)d_in[2];
    const int* receivers      = (const int*)d_in[3];
    const float* embed_w      = (const float*)d_in[4];
    const float* w_res_s      = (const float*)d_in[5];
    const float* w_res_v      = (const float*)d_in[6];
    const float* w_lin1_s     = (const float*)d_in[7];
    const float* w_lin1_v     = (const float*)d_in[8];
    const float* mlp_w0       = (const float*)d_in[9];
    const float* mlp_w1       = (const float*)d_in[10];
    const float* mlp_w2       = (const float*)d_in[11];
    const float* w_lin2_s     = (const float*)d_in[12];
    const float* w_lin2_v     = (const float*)d_in[13];
    const float* w_out1       = (const float*)d_in[14];
    const float* w_out2       = (const float*)d_in[15];
    float* out = (float*)d_out;

    const int NB256 = (NN + 255) / 256;
    const int EB256 = (EE + 255) / 256;
    const int WPB = (NN / 4 + 7) / 8;   // 4-node-per-warp kernels: 12500 warps
    const int GPB = (NN + 7) / 8;       // warp-per-node gather: 50000 warps

    // CSR + species sort + tables (recomputed every call; deterministic inputs)
    k_zero<<<NB256, 256>>>();
    k_hist<<<EB256, 256>>>(edge_vectors, receivers);
    k_spec_hist<<<NB256, 256>>>(species);
    k_scan<<<1, 1024>>>();
    k_spec_scatter<<<NB256, 256>>>(species);
    k_scatter<<<EB256, 256>>>(edge_vectors, senders, receivers);
    k_build_table<<<TBINS, 128>>>(mlp_w0, mlp_w1, mlp_w2, 0);
    k_build_table<<<TBINS, 128>>>(mlp_w0, mlp_w1, mlp_w2, 1);
    k_node_init<<<(NN * 32 + 255) / 256, 256>>>(species, embed_w);

    // layer 0 (h_v == 0)
    k_node_prep<false><<<WPB, 256>>>(species, w_res_s, w_res_v, w_lin1_s, w_lin1_v, 0);
    k_gather<false><<<GPB, 256>>>();
    k_node_update<false><<<WPB, 256>>>(w_lin2_s, w_lin2_v, w_out1, w_out2, out, 0);

    // layer 1 (full) + fused readout
    k_node_prep<true><<<WPB, 256>>>(species, w_res_s, w_res_v, w_lin1_s, w_lin1_v, 1);
    k_gather<true><<<GPB, 256>>>();
    k_node_update<true><<<WPB, 256>>>(w_lin2_s, w_lin2_v, w_out1, w_out2, out, 1);
}

// round 4
// speedup vs baseline: 5.7555x; 1.7787x over previous
#include <cuda_runtime.h>

#define NN 50000
#define EE 800000
#define SC 5
#define NBC 8
#define HC 64
#define NWC 128
#define TBINS 2048
#define RMAXF 5.0f

// ---------------- device scratch ----------------
__device__ float g_hs[NN * 32];          // layer0 output h_s
__device__ float g_hv[NN * 96];          // layer0 output h_v [n][i][u]
__device__ float4 g_feat[NN * 32];       // layer1 lin1 feats: (es, ev0, ev1, ev2)
__device__ float g_res1s[NN * 32];       // layer1 residual scalars (first half only)
__device__ float g_n0a[NN * 32];         // layer0 gather out (scalars)
__device__ float g_n1a[NN * 96];         // layer0 gather out (vectors) [n][i][u]
__device__ float g_n0b[NN * 64];         // layer1 gather out (scalars, both halves)
__device__ float g_tab0[TBINS * 64];     // layer0 LUT [bin][u][2] = (w1, w3)
__device__ float g_tab1[TBINS * 64];     // layer1 LUT [bin][u][2] = (w1, w2)
__device__ float g_s0hsl[SC * 32];       // species-pure layer0 lin1 scalars
__device__ float g_s0res[SC * 64];       // species-pure layer0 residual scalars
__device__ int g_cnt[NN];
__device__ int g_off[NN + 1];
__device__ int g_bsum[64];
__device__ int g_boff[64];
__device__ float4 g_epack[EE];           // CSR (p, sh0, sh1, sh2)
__device__ int g_esend[EE];
__device__ int g_nsort[NN];
__device__ int g_scnt[SC];
__device__ int g_scur[SC];

__device__ __forceinline__ float silu(float x) { return x / (1.0f + __expf(-x)); }

// ---------------- build: zero / hist / scan / scatter ----------------
__global__ void k_zero() {
    int t = blockIdx.x * blockDim.x + threadIdx.x;
    if (t < NN) g_cnt[t] = 0;
    if (t < SC) g_scnt[t] = 0;
}

__global__ void k_hist(const float* __restrict__ evec, const int* __restrict__ recv,
                       const int* __restrict__ species) {
    int e = blockIdx.x * blockDim.x + threadIdx.x;
    if (e < NN) atomicAdd(&g_scnt[species[e]], 1);
    if (e >= EE) return;
    float x = evec[e * 3], y = evec[e * 3 + 1], z = evec[e * 3 + 2];
    if (x * x + y * y + z * z < RMAXF * RMAXF) atomicAdd(&g_cnt[recv[e]], 1);
}

__global__ void k_scan1() {  // 49 blocks x 1024
    __shared__ int wsum[32];
    int t = threadIdx.x, lane = t & 31, wid = t >> 5;
    int idx = blockIdx.x * 1024 + t;
    int v = (idx < NN) ? g_cnt[idx] : 0;
    int x = v;
#pragma unroll
    for (int d = 1; d < 32; d <<= 1) {
        int y = __shfl_up_sync(0xffffffffu, x, d);
        if (lane >= d) x += y;
    }
    if (lane == 31) wsum[wid] = x;
    __syncthreads();
    if (wid == 0) {
        int s = wsum[lane];
#pragma unroll
        for (int d = 1; d < 32; d <<= 1) {
            int y = __shfl_up_sync(0xffffffffu, s, d);
            if (lane >= d) s += y;
        }
        wsum[lane] = s;
    }
    __syncthreads();
    int incl = x + (wid > 0 ? wsum[wid - 1] : 0);
    if (idx < NN) g_off[idx] = incl - v;  // block-local exclusive
    if (t == 1023) g_bsum[blockIdx.x] = incl;
}

__global__ void k_scan2() {  // 1 block, 64 threads
    __shared__ int sh[64];
    int t = threadIdx.x;
    sh[t] = (t < 49) ? g_bsum[t] : 0;
    __syncthreads();
    if (t == 0) {
        int acc = 0;
        for (int b = 0; b < 49; b++) { g_boff[b] = acc; acc += sh[b]; }
        g_off[NN] = acc;
        int a2 = 0;
        for (int s = 0; s < SC; s++) { int c = g_scnt[s]; g_scnt[s] = a2; g_scur[s] = a2; a2 += c; }
    }
}

__global__ void k_scan3() {  // 49 blocks x 1024
    int idx = blockIdx.x * 1024 + threadIdx.x;
    if (idx < NN) {
        int o = g_off[idx] + g_boff[blockIdx.x];
        g_off[idx] = o;
        g_cnt[idx] = o;
    }
}

__global__ void k_scatter(const float* __restrict__ evec, const int* __restrict__ senders,
                          const int* __restrict__ recv, const int* __restrict__ species) {
    int e = blockIdx.x * blockDim.x + threadIdx.x;
    if (e < NN) {
        int pos = atomicAdd(&g_scur[species[e]], 1);
        g_nsort[pos] = e;
    }
    if (e >= EE) return;
    float x = evec[e * 3], y = evec[e * 3 + 1], z = evec[e * 3 + 2];
    float r2 = x * x + y * y + z * z;
    if (r2 >= RMAXF * RMAXF) return;
    float r = sqrtf(r2 + 1e-12f);
    float ir = 1.0f / r;
    const float SQ3 = 1.7320508075688772f;
    int pos = atomicAdd(&g_cnt[recv[e]], 1);
    g_epack[pos] = make_float4(r * ((float)(TBINS - 1) / RMAXF), SQ3 * x * ir, SQ3 * y * ir, SQ3 * z * ir);
    g_esend[pos] = senders[e];
}

// ---------------- radial-MLP LUT (both layers in one launch) ----------------
__global__ void k_build_table(const float* __restrict__ mlp_w0,
                              const float* __restrict__ mlp_w1,
                              const float* __restrict__ mlp_w2) {
    __shared__ float a1[HC];
    __shared__ float a2[HC];
    __shared__ float eemb[NBC];
    int bin = blockIdx.x;
    int l = blockIdx.y;
    int tid = threadIdx.x;
    const float* w0 = mlp_w0 + l * NBC * HC;
    const float* w1 = mlp_w1 + l * HC * HC;
    const float* w2 = mlp_w2 + l * HC * NWC;
    if (tid < NBC) {
        float r = (float)bin * (RMAXF / (float)(TBINS - 1));
        float rs = fmaxf(r, 1e-6f);
        float ir = 1.0f / rs;
        float xr = rs * (1.0f / RMAXF);
        float x3 = xr * xr * xr, x6 = x3 * x3, x7 = x6 * xr, x8 = x7 * xr;
        float env = 1.0f - 28.0f * x6 + 48.0f * x7 - 21.0f * x8;
        const float PI_ = 3.14159265358979323846f;
        eemb[tid] = 0.6324555320336759f * ir * env * sinf(PI_ * xr * (float)(tid + 1));
    }
    __syncthreads();
    if (tid < HC) {
        float acc = 0.f;
#pragma unroll
        for (int k = 0; k < NBC; k++) acc += eemb[k] * w0[k * HC + tid];
        a1[tid] = silu(acc * 0.35355339059327373f);
    }
    __syncthreads();
    if (tid < HC) {
        float acc = 0.f;
#pragma unroll 8
        for (int k = 0; k < HC; k++) acc += a1[k] * w1[k * HC + tid];
        a2[tid] = silu(acc * 0.125f);
    }
    __syncthreads();
    {
        float acc = 0.f;
#pragma unroll 8
        for (int k = 0; k < HC; k++) acc += a2[k] * w2[k * NWC + tid];
        int u = tid & 31, path = tid >> 5;
        if (l == 0) {  // layer0 needs (w1, w3); w2/w4 multiply zero vectors
            if (path == 0) g_tab0[bin * 64 + u * 2 + 0] = acc;
            else if (path == 2) g_tab0[bin * 64 + u * 2 + 1] = acc;
        } else {       // layer1 needs (w1, w2); w3/w4 feed dead v_out
            if (path == 0) g_tab1[bin * 64 + u * 2 + 0] = acc;
            else if (path == 1) g_tab1[bin * 64 + u * 2 + 1] = acc;
        }
    }
}

// ---------------- layer0 species-pure node prep (5 warps total) ----------------
__global__ void k_spec0(const float* __restrict__ embed_w,
                        const float* __restrict__ w_lin1_s,
                        const float* __restrict__ w_res_s) {
    int w = threadIdx.x >> 5, lane = threadIdx.x & 31;
    if (w >= SC) return;
    float a_hs = 0.f, a_rs0 = 0.f, a_rs1 = 0.f;
#pragma unroll 4
    for (int u = 0; u < 32; u++) {
        float x = embed_w[w * 32 + u] * 0.4472135954999579f;  // /sqrt(5)
        a_hs += x * w_lin1_s[u * 32 + lane];
        const float* rs = w_res_s + (size_t)(u * SC + w) * 64;
        a_rs0 += x * rs[lane];
        a_rs1 += x * rs[32 + lane];
    }
    g_s0hsl[w * 32 + lane] = a_hs * 0.17677669529663687f;       // /sqrt(32)
    g_s0res[w * 64 + lane] = a_rs0 * 0.07905694150420949f;      // /sqrt(160)
    g_s0res[w * 64 + 32 + lane] = a_rs1 * 0.07905694150420949f;
}

// ---------------- layer0 gather: species-pure sender feats, (w1,w3) paths ----------------
__global__ void __launch_bounds__(256) k_gather0(const int* __restrict__ species) {
    int n = (blockIdx.x * blockDim.x + threadIdx.x) >> 5;
    int lane = threadIdx.x & 31;
    if (n >= NN) return;
    int e = g_off[n], end = g_off[n + 1];
    float a0 = 0.f, c3x = 0.f, c3y = 0.f, c3z = 0.f;
    for (; e + 1 < end; e += 2) {
        float4 pA = __ldg(&g_epack[e]);
        float4 pB = __ldg(&g_epack[e + 1]);
        int sA = __ldg(&g_esend[e]);
        int sB = __ldg(&g_esend[e + 1]);
        int iA = min((int)pA.x, TBINS - 2);
        int iB = min((int)pB.x, TBINS - 2);
        float fA = pA.x - (float)iA, fB = pB.x - (float)iB;
        float2 tA0 = *reinterpret_cast<const float2*>(&g_tab0[iA * 64 + lane * 2]);
        float2 tA1 = *reinterpret_cast<const float2*>(&g_tab0[(iA + 1) * 64 + lane * 2]);
        float2 tB0 = *reinterpret_cast<const float2*>(&g_tab0[iB * 64 + lane * 2]);
        float2 tB1 = *reinterpret_cast<const float2*>(&g_tab0[(iB + 1) * 64 + lane * 2]);
        float esA = g_s0hsl[species[sA] * 32 + lane];
        float esB = g_s0hsl[species[sB] * 32 + lane];
        float w1A = fmaf(fA, tA1.x - tA0.x, tA0.x);
        float w3A = fmaf(fA, tA1.y - tA0.y, tA0.y);
        float w1B = fmaf(fB, tB1.x - tB0.x, tB0.x);
        float w3B = fmaf(fB, tB1.y - tB0.y, tB0.y);
        a0 += w1A * esA + w1B * esB;
        float wA = w3A * esA, wB = w3B * esB;
        c3x += wA * pA.y + wB * pB.y;
        c3y += wA * pA.z + wB * pB.z;
        c3z += wA * pA.w + wB * pB.w;
    }
    if (e < end) {
        float4 pA = __ldg(&g_epack[e]);
        int sA = __ldg(&g_esend[e]);
        int iA = min((int)pA.x, TBINS - 2);
        float fA = pA.x - (float)iA;
        float2 tA0 = *reinterpret_cast<const float2*>(&g_tab0[iA * 64 + lane * 2]);
        float2 tA1 = *reinterpret_cast<const float2*>(&g_tab0[(iA + 1) * 64 + lane * 2]);
        float esA = g_s0hsl[species[sA] * 32 + lane];
        float w1A = fmaf(fA, tA1.x - tA0.x, tA0.x);
        float w3A = fmaf(fA, tA1.y - tA0.y, tA0.y);
        a0 += w1A * esA;
        float wA = w3A * esA;
        c3x += wA * pA.y; c3y += wA * pA.z; c3z += wA * pA.w;
    }
    g_n0a[n * 32 + lane] = a0;
    g_n1a[(n * 3 + 0) * 32 + lane] = c3x;
    g_n1a[(n * 3 + 1) * 32 + lane] = c3y;
    g_n1a[(n * 3 + 2) * 32 + lane] = c3z;
}

// ---------------- layer0 update: lin2(j<32) + species residual + gate (8 nodes/warp) ----------------
__global__ void __launch_bounds__(256) k_update0(const int* __restrict__ species,
                                                 const float* __restrict__ w_lin2_s,
                                                 const float* __restrict__ w_lin2_v) {
    int w = (blockIdx.x * blockDim.x + threadIdx.x) >> 5;
    int lane = threadIdx.x & 31;
    int base = w * 8;
    if (base >= NN) return;
    float s0[8] = {0}, s1[8] = {0}, vv[8][3] = {{0}};
#pragma unroll 2
    for (int jc = 0; jc < 8; jc++) {
        int j0 = jc * 4;
        float wa[4], wb[4], wc[4];
#pragma unroll
        for (int d = 0; d < 4; d++) {
            wa[d] = w_lin2_s[(j0 + d) * 64 + lane];
            wb[d] = w_lin2_s[(j0 + d) * 64 + 32 + lane];
            wc[d] = w_lin2_v[(j0 + d) * 32 + lane];
        }
#pragma unroll
        for (int g = 0; g < 8; g++) {
            int n = base + g;
            float4 x = *reinterpret_cast<const float4*>(&g_n0a[n * 32 + j0]);
            s0[g] += x.x * wa[0] + x.y * wa[1] + x.z * wa[2] + x.w * wa[3];
            s1[g] += x.x * wb[0] + x.y * wb[1] + x.z * wb[2] + x.w * wb[3];
#pragma unroll
            for (int i = 0; i < 3; i++) {
                float4 xv = *reinterpret_cast<const float4*>(&g_n1a[(n * 3 + i) * 32 + j0]);
                vv[g][i] += xv.x * wc[0] + xv.y * wc[1] + xv.z * wc[2] + xv.w * wc[3];
            }
        }
    }
    const float SC_ = 0.0078125f;  // (1/16)*(1/sqrt(64))
#pragma unroll
    for (int g = 0; g < 8; g++) {
        int n = base + g;
        int sp = species[n];
        float so0 = s0[g] * SC_ + g_s0res[sp * 64 + lane];
        float so1 = s1[g] * SC_ + g_s0res[sp * 64 + 32 + lane];
        float hs = silu(so0);
        float gate = silu(so1);
        g_hs[n * 32 + lane] = hs;
#pragma unroll
        for (int i = 0; i < 3; i++)
            g_hv[(n * 3 + i) * 32 + lane] = vv[g][i] * SC_ * gate;  // res_v == 0 at layer0
    }
}

// ---------------- layer1 prep: lin1 + residual(first half) (8 nodes/warp, species-sorted) ----------------
__global__ void __launch_bounds__(256) k_prep1(const int* __restrict__ species,
                                               const float* __restrict__ w_res_s,
                                               const float* __restrict__ w_lin1_s,
                                               const float* __restrict__ w_lin1_v) {
    int w = (blockIdx.x * blockDim.x + threadIdx.x) >> 5;
    int lane = threadIdx.x & 31;
    int base = w * 8;
    if (base >= NN) return;
    int nid[8], sp[8];
#pragma unroll
    for (int g = 0; g < 8; g++) { nid[g] = g_nsort[base + g]; sp[g] = species[nid[g]]; }
    bool uni = true;
#pragma unroll
    for (int g = 1; g < 8; g++) uni = uni && (sp[g] == sp[0]);
    const float* Wl1s = w_lin1_s + 1024;
    const float* Wl1v = w_lin1_v + 1024;
    float a_hs[8] = {0}, a_rs0[8] = {0}, a_hv[8][3] = {{0}};
#pragma unroll 2
    for (int uc = 0; uc < 8; uc++) {
        int u0 = uc * 4;
        float ws[4], wv[4], wr0[4];
#pragma unroll
        for (int d = 0; d < 4; d++) {
            ws[d] = Wl1s[(u0 + d) * 32 + lane];
            wv[d] = Wl1v[(u0 + d) * 32 + lane];
        }
        if (uni) {
#pragma unroll
            for (int d = 0; d < 4; d++)
                wr0[d] = w_res_s[(size_t)(((32 + u0 + d) * SC) + sp[0]) * 64 + lane];
        }
#pragma unroll
        for (int g = 0; g < 8; g++) {
            float r0[4];
            if (uni) {
#pragma unroll
                for (int d = 0; d < 4; d++) r0[d] = wr0[d];
            } else {
#pragma unroll
                for (int d = 0; d < 4; d++)
                    r0[d] = w_res_s[(size_t)(((32 + u0 + d) * SC) + sp[g]) * 64 + lane];
            }
            float4 xs = *reinterpret_cast<const float4*>(&g_hs[nid[g] * 32 + u0]);
            float xa[4] = {xs.x, xs.y, xs.z, xs.w};
#pragma unroll
            for (int d = 0; d < 4; d++) {
                a_hs[g] += xa[d] * ws[d];
                a_rs0[g] += xa[d] * r0[d];
            }
#pragma unroll
            for (int i = 0; i < 3; i++) {
                float4 xv = *reinterpret_cast<const float4*>(&g_hv[(nid[g] * 3 + i) * 32 + u0]);
                a_hv[g][i] += xv.x * wv[0] + xv.y * wv[1] + xv.z * wv[2] + xv.w * wv[3];
            }
        }
    }
    const float IS32 = 0.17677669529663687f;
    const float IS160 = 0.07905694150420949f;
#pragma unroll
    for (int g = 0; g < 8; g++) {
        int n = nid[g];
        g_feat[n * 32 + lane] = make_float4(a_hs[g] * IS32, a_hv[g][0] * IS32,
                                            a_hv[g][1] * IS32, a_hv[g][2] * IS32);
        g_res1s[n * 32 + lane] = a_rs0[g] * IS160;
    }
}

// ---------------- layer1 gather: packed feats, (w1,w2) paths only ----------------
__global__ void __launch_bounds__(256) k_gather1() {
    int n = (blockIdx.x * blockDim.x + threadIdx.x) >> 5;
    int lane = threadIdx.x & 31;
    if (n >= NN) return;
    int e = g_off[n], end = g_off[n + 1];
    float a0 = 0.f, a1 = 0.f;
    for (; e + 1 < end; e += 2) {
        float4 pA = __ldg(&g_epack[e]);
        float4 pB = __ldg(&g_epack[e + 1]);
        int sA = __ldg(&g_esend[e]);
        int sB = __ldg(&g_esend[e + 1]);
        int iA = min((int)pA.x, TBINS - 2);
        int iB = min((int)pB.x, TBINS - 2);
        float fA = pA.x - (float)iA, fB = pB.x - (float)iB;
        float2 tA0 = *reinterpret_cast<const float2*>(&g_tab1[iA * 64 + lane * 2]);
        float2 tA1 = *reinterpret_cast<const float2*>(&g_tab1[(iA + 1) * 64 + lane * 2]);
        float2 tB0 = *reinterpret_cast<const float2*>(&g_tab1[iB * 64 + lane * 2]);
        float2 tB1 = *reinterpret_cast<const float2*>(&g_tab1[(iB + 1) * 64 + lane * 2]);
        float4 ftA = __ldg(&g_feat[sA * 32 + lane]);
        float4 ftB = __ldg(&g_feat[sB * 32 + lane]);
        float w1A = fmaf(fA, tA1.x - tA0.x, tA0.x);
        float w2A = fmaf(fA, tA1.y - tA0.y, tA0.y);
        float w1B = fmaf(fB, tB1.x - tB0.x, tB0.x);
        float w2B = fmaf(fB, tB1.y - tB0.y, tB0.y);
        a0 += w1A * ftA.x + w1B * ftB.x;
        float dA = ftA.y * pA.y + ftA.z * pA.z + ftA.w * pA.w;
        float dB = ftB.y * pB.y + ftB.z * pB.z + ftB.w * pB.w;
        a1 += w2A * dA + w2B * dB;
    }
    if (e < end) {
        float4 pA = __ldg(&g_epack[e]);
        int sA = __ldg(&g_esend[e]);
        int iA = min((int)pA.x, TBINS - 2);
        float fA = pA.x - (float)iA;
        float2 tA0 = *reinterpret_cast<const float2*>(&g_tab1[iA * 64 + lane * 2]);
        float2 tA1 = *reinterpret_cast<const float2*>(&g_tab1[(iA + 1) * 64 + lane * 2]);
        float4 ftA = __ldg(&g_feat[sA * 32 + lane]);
        float w1A = fmaf(fA, tA1.x - tA0.x, tA0.x);
        float w2A = fmaf(fA, tA1.y - tA0.y, tA0.y);
        a0 += w1A * ftA.x;
        a1 += w2A * (ftA.y * pA.y + ftA.z * pA.z + ftA.w * pA.w);
    }
    g_n0b[n * 64 + lane] = a0;
    g_n0b[n * 64 + 32 + lane] = a1 * 0.5773502691896258f;  // 1/sqrt(3)
}

// ---------------- layer1 update + readout (8 nodes/warp; gate/vector paths dead) ----------------
__global__ void __launch_bounds__(256) k_update1(const float* __restrict__ w_lin2_s,
                                                 const float* __restrict__ w_out1,
                                                 const float* __restrict__ w_out2,
                                                 float* __restrict__ out) {
    int w = (blockIdx.x * blockDim.x + threadIdx.x) >> 5;
    int lane = threadIdx.x & 31;
    int base = w * 8;
    if (base >= NN) return;
    const float* W2s = w_lin2_s + 4096;  // l=1
    float s0[8] = {0};
#pragma unroll 4
    for (int jc = 0; jc < 16; jc++) {
        int j0 = jc * 4;
        float wa[4];
#pragma unroll
        for (int d = 0; d < 4; d++) wa[d] = W2s[(j0 + d) * 64 + lane];
#pragma unroll
        for (int g = 0; g < 8; g++) {
            float4 x = *reinterpret_cast<const float4*>(&g_n0b[(base + g) * 64 + j0]);
            s0[g] += x.x * wa[0] + x.y * wa[1] + x.z * wa[2] + x.w * wa[3];
        }
    }
    float wcomb = 0.f;
#pragma unroll
    for (int k = 0; k < 16; k++) wcomb += w_out1[lane * 16 + k] * w_out2[k];
    const float SC_ = 0.0078125f;
#pragma unroll
    for (int g = 0; g < 8; g++) {
        int n = base + g;
        float hs = silu(s0[g] * SC_ + g_res1s[n * 32 + lane]);
        float z = hs * wcomb;
        z += __shfl_xor_sync(0xffffffffu, z, 16);
        z += __shfl_xor_sync(0xffffffffu, z, 8);
        z += __shfl_xor_sync(0xffffffffu, z, 4);
        z += __shfl_xor_sync(0xffffffffu, z, 2);
        z += __shfl_xor_sync(0xffffffffu, z, 1);
        if (lane == 0) out[n] = z * (0.17677669529663687f * 0.25f);  // /sqrt(32)/sqrt(16)
    }
}

// ---------------- launch ----------------
extern "C" void kernel_launch(void* const* d_in, const int* in_sizes, int n_in,
                              void* d_out, int out_size) {
    const float* edge_vectors = (const float*)d_in[0];
    const int* species        = (const int*)d_in[1];
    const int* senders        = (const int*)d_in[2];
    const int* receivers      = (const int*)d_in[3];
    const float* embed_w      = (const float*)d_in[4];
    const float* w_res_s      = (const float*)d_in[5];
    const float* w_lin1_s     = (const float*)d_in[7];
    const float* w_lin1_v     = (const float*)d_in[8];
    const float* mlp_w0       = (const float*)d_in[9];
    const float* mlp_w1       = (const float*)d_in[10];
    const float* mlp_w2       = (const float*)d_in[11];
    const float* w_lin2_s     = (const float*)d_in[12];
    const float* w_lin2_v     = (const float*)d_in[13];
    const float* w_out1       = (const float*)d_in[14];
    const float* w_out2       = (const float*)d_in[15];
    float* out = (float*)d_out;

    const int EB256 = (EE + 255) / 256;
    const int GPB = (NN + 7) / 8;          // warp-per-node: 6250 blocks
    const int WPB8 = (NN / 8 + 7) / 8;     // 8-node-per-warp: 782 blocks

    k_zero<<<(NN + 255) / 256, 256>>>();
    k_hist<<<EB256, 256>>>(edge_vectors, receivers, species);
    k_scan1<<<49, 1024>>>();
    k_scan2<<<1, 64>>>();
    k_scan3<<<49, 1024>>>();
    k_scatter<<<EB256, 256>>>(edge_vectors, senders, receivers, species);
    k_build_table<<<dim3(TBINS, 2), 128>>>(mlp_w0, mlp_w1, mlp_w2);
    k_spec0<<<1, 160>>>(embed_w, w_lin1_s, w_res_s);

    // layer 0
    k_gather0<<<GPB, 256>>>(species);
    k_update0<<<WPB8, 256>>>(species, w_lin2_s, w_lin2_v);

    // layer 1 (gate/vector outputs dead -> scalar-only pipeline)
    k_prep1<<<WPB8, 256>>>(species, w_res_s, w_lin1_s, w_lin1_v);
    k_gather1<<<GPB, 256>>>();
    k_update1<<<WPB8, 256>>>(w_lin2_s, w_out1, w_out2, out);
}

// round 6
// speedup vs baseline: 5.7793x; 1.0041x over previous
#include <cuda_runtime.h>
#include <cuda_fp16.h>

#define NN 50000
#define EE 800000
#define SC 5
#define NBC 8
#define HC 64
#define NWC 128
#define TBINS 2048
#define RMAXF 5.0f

// ---------------- device scratch ----------------
__device__ float g_hs[NN * 32];          // layer0 output h_s
__device__ float g_hv[NN * 96];          // layer0 output h_v [n][i][u]
__device__ __half2 g_feath[NN * 64];     // layer1 feats: lane -> (es,ev0),(ev1,ev2)
__device__ float g_res1s[NN * 32];       // layer1 residual scalars
__device__ float g_n0a[NN * 32];         // layer0 gather out (scalars)
__device__ float g_n1a[NN * 96];         // layer0 gather out (vectors)
__device__ float g_n0b[NN * 64];         // layer1 gather out
__device__ __half2 g_tab0h[TBINS * 32];  // layer0 LUT row: lane -> (w1, w3)
__device__ __half2 g_tab1h[TBINS * 32];  // layer1 LUT row: lane -> (w1, w2)
__device__ float g_s0hsl[SC * 32];       // species-pure layer0 lin1 scalars
__device__ float g_s0res[SC * 64];       // species-pure layer0 residual scalars
__device__ int g_cnt[NN];
__device__ int g_off[NN + 1];
__device__ int g_bsum[64];
__device__ int g_boff[64];
__device__ float4 g_epack[EE];           // CSR (p, sh0, sh1, sh2)
__device__ int g_esend[EE];              // CSR sender id (layer1)
__device__ unsigned char g_espec[EE];    // CSR sender species (layer0)
__device__ int g_nsort[NN];
__device__ int g_scnt[SC];
__device__ int g_scur[SC];

__device__ __forceinline__ float silu(float x) { return x / (1.0f + __expf(-x)); }

// ---------------- build: zero / hist / scan / scatter ----------------
__global__ void k_zero() {
    int t = blockIdx.x * blockDim.x + threadIdx.x;
    if (t < NN) g_cnt[t] = 0;
    if (t < SC) g_scnt[t] = 0;
}

__global__ void k_hist(const float* __restrict__ evec, const int* __restrict__ recv,
                       const int* __restrict__ species) {
    int e = blockIdx.x * blockDim.x + threadIdx.x;
    if (e < NN) atomicAdd(&g_scnt[species[e]], 1);
    if (e >= EE) return;
    float x = evec[e * 3], y = evec[e * 3 + 1], z = evec[e * 3 + 2];
    if (x * x + y * y + z * z < RMAXF * RMAXF) atomicAdd(&g_cnt[recv[e]], 1);
}

__global__ void k_scan1() {  // 49 blocks x 1024
    __shared__ int wsum[32];
    int t = threadIdx.x, lane = t & 31, wid = t >> 5;
    int idx = blockIdx.x * 1024 + t;
    int v = (idx < NN) ? g_cnt[idx] : 0;
    int x = v;
#pragma unroll
    for (int d = 1; d < 32; d <<= 1) {
        int y = __shfl_up_sync(0xffffffffu, x, d);
        if (lane >= d) x += y;
    }
    if (lane == 31) wsum[wid] = x;
    __syncthreads();
    if (wid == 0) {
        int s = wsum[lane];
#pragma unroll
        for (int d = 1; d < 32; d <<= 1) {
            int y = __shfl_up_sync(0xffffffffu, s, d);
            if (lane >= d) s += y;
        }
        wsum[lane] = s;
    }
    __syncthreads();
    int incl = x + (wid > 0 ? wsum[wid - 1] : 0);
    if (idx < NN) g_off[idx] = incl - v;
    if (t == 1023) g_bsum[blockIdx.x] = incl;
}

__global__ void k_scan2() {
    int t = threadIdx.x;
    if (t == 0) {
        int acc = 0;
        for (int b = 0; b < 49; b++) { g_boff[b] = acc; acc += g_bsum[b]; }
        g_off[NN] = acc;
        int a2 = 0;
        for (int s = 0; s < SC; s++) { int c = g_scnt[s]; g_scnt[s] = a2; g_scur[s] = a2; a2 += c; }
    }
}

__global__ void k_scan3() {
    int idx = blockIdx.x * 1024 + threadIdx.x;
    if (idx < NN) {
        int o = g_off[idx] + g_boff[blockIdx.x];
        g_off[idx] = o;
        g_cnt[idx] = o;
    }
}

__global__ void k_scatter(const float* __restrict__ evec, const int* __restrict__ senders,
                          const int* __restrict__ recv, const int* __restrict__ species) {
    int e = blockIdx.x * blockDim.x + threadIdx.x;
    if (e < NN) {
        int pos = atomicAdd(&g_scur[species[e]], 1);
        g_nsort[pos] = e;
    }
    if (e >= EE) return;
    float x = evec[e * 3], y = evec[e * 3 + 1], z = evec[e * 3 + 2];
    float r2 = x * x + y * y + z * z;
    if (r2 >= RMAXF * RMAXF) return;
    float r = sqrtf(r2 + 1e-12f);
    float ir = 1.0f / r;
    const float SQ3 = 1.7320508075688772f;
    int s = senders[e];
    int pos = atomicAdd(&g_cnt[recv[e]], 1);
    g_epack[pos] = make_float4(r * ((float)(TBINS - 1) / RMAXF), SQ3 * x * ir, SQ3 * y * ir, SQ3 * z * ir);
    g_esend[pos] = s;
    g_espec[pos] = (unsigned char)species[s];
}

// ---------------- radial-MLP LUT (fp16 rows, both layers) ----------------
__global__ void k_build_table(const float* __restrict__ mlp_w0,
                              const float* __restrict__ mlp_w1,
                              const float* __restrict__ mlp_w2) {
    __shared__ float a1[HC];
    __shared__ float a2[HC];
    __shared__ float eemb[NBC];
    __shared__ float sacc[128];
    int bin = blockIdx.x;
    int l = blockIdx.y;
    int tid = threadIdx.x;
    const float* w0 = mlp_w0 + l * NBC * HC;
    const float* w1 = mlp_w1 + l * HC * HC;
    const float* w2 = mlp_w2 + l * HC * NWC;
    if (tid < NBC) {
        float r = (float)bin * (RMAXF / (float)(TBINS - 1));
        float rs = fmaxf(r, 1e-6f);
        float ir = 1.0f / rs;
        float xr = rs * (1.0f / RMAXF);
        float x3 = xr * xr * xr, x6 = x3 * x3, x7 = x6 * xr, x8 = x7 * xr;
        float env = 1.0f - 28.0f * x6 + 48.0f * x7 - 21.0f * x8;
        const float PI_ = 3.14159265358979323846f;
        eemb[tid] = 0.6324555320336759f * ir * env * sinf(PI_ * xr * (float)(tid + 1));
    }
    __syncthreads();
    if (tid < HC) {
        float acc = 0.f;
#pragma unroll
        for (int k = 0; k < NBC; k++) acc += eemb[k] * w0[k * HC + tid];
        a1[tid] = silu(acc * 0.35355339059327373f);
    }
    __syncthreads();
    if (tid < HC) {
        float acc = 0.f;
#pragma unroll 8
        for (int k = 0; k < HC; k++) acc += a1[k] * w1[k * HC + tid];
        a2[tid] = silu(acc * 0.125f);
    }
    __syncthreads();
    {
        float acc = 0.f;
#pragma unroll 8
        for (int k = 0; k < HC; k++) acc += a2[k] * w2[k * NWC + tid];
        sacc[tid] = acc;
    }
    __syncthreads();
    if (tid < 32) {
        if (l == 0)  // (w1, w3); w2/w4 multiply zero vectors at layer0
            g_tab0h[bin * 32 + tid] = __floats2half2_rn(sacc[tid], sacc[64 + tid]);
        else         // (w1, w2); w3/w4 feed dead layer1 v_out
            g_tab1h[bin * 32 + tid] = __floats2half2_rn(sacc[tid], sacc[32 + tid]);
    }
}

// ---------------- layer0 species-pure node prep (5 warps) ----------------
__global__ void k_spec0(const float* __restrict__ embed_w,
                        const float* __restrict__ w_lin1_s,
                        const float* __restrict__ w_res_s) {
    int w = threadIdx.x >> 5, lane = threadIdx.x & 31;
    if (w >= SC) return;
    float a_hs = 0.f, a_rs0 = 0.f, a_rs1 = 0.f;
#pragma unroll 4
    for (int u = 0; u < 32; u++) {
        float x = embed_w[w * 32 + u] * 0.4472135954999579f;
        a_hs += x * w_lin1_s[u * 32 + lane];
        const float* rs = w_res_s + (size_t)(u * SC + w) * 64;
        a_rs0 += x * rs[lane];
        a_rs1 += x * rs[32 + lane];
    }
    g_s0hsl[w * 32 + lane] = a_hs * 0.17677669529663687f;
    g_s0res[w * 64 + lane] = a_rs0 * 0.07905694150420949f;
    g_s0res[w * 64 + 32 + lane] = a_rs1 * 0.07905694150420949f;
}

// ---------------- layer0 gather: species feats in registers, fp16 LUT ----------------
__global__ void __launch_bounds__(256) k_gather0() {
    int n = (blockIdx.x * blockDim.x + threadIdx.x) >> 5;
    int lane = threadIdx.x & 31;
    if (n >= NN) return;
    float s0r0 = g_s0hsl[lane];
    float s0r1 = g_s0hsl[32 + lane];
    float s0r2 = g_s0hsl[64 + lane];
    float s0r3 = g_s0hsl[96 + lane];
    float s0r4 = g_s0hsl[128 + lane];
    int e = g_off[n], end = g_off[n + 1];
    float a0 = 0.f, c3x = 0.f, c3y = 0.f, c3z = 0.f;
    for (; e + 1 < end; e += 2) {
        float4 pA = __ldg(&g_epack[e]);
        float4 pB = __ldg(&g_epack[e + 1]);
        int spA = (int)g_espec[e];
        int spB = (int)g_espec[e + 1];
        int iA = (int)pA.x, iB = (int)pB.x;
        float fA = pA.x - (float)iA, fB = pB.x - (float)iB;
        float2 tA0 = __half22float2(g_tab0h[iA * 32 + lane]);
        float2 tA1 = __half22float2(g_tab0h[(iA + 1) * 32 + lane]);
        float2 tB0 = __half22float2(g_tab0h[iB * 32 + lane]);
        float2 tB1 = __half22float2(g_tab0h[(iB + 1) * 32 + lane]);
        float esA = s0r0;
        esA = (spA == 1) ? s0r1 : esA;
        esA = (spA == 2) ? s0r2 : esA;
        esA = (spA == 3) ? s0r3 : esA;
        esA = (spA == 4) ? s0r4 : esA;
        float esB = s0r0;
        esB = (spB == 1) ? s0r1 : esB;
        esB = (spB == 2) ? s0r2 : esB;
        esB = (spB == 3) ? s0r3 : esB;
        esB = (spB == 4) ? s0r4 : esB;
        float w1A = fmaf(fA, tA1.x - tA0.x, tA0.x);
        float w3A = fmaf(fA, tA1.y - tA0.y, tA0.y);
        float w1B = fmaf(fB, tB1.x - tB0.x, tB0.x);
        float w3B = fmaf(fB, tB1.y - tB0.y, tB0.y);
        a0 += w1A * esA + w1B * esB;
        float wA = w3A * esA, wB = w3B * esB;
        c3x += wA * pA.y + wB * pB.y;
        c3y += wA * pA.z + wB * pB.z;
        c3z += wA * pA.w + wB * pB.w;
    }
    if (e < end) {
        float4 pA = __ldg(&g_epack[e]);
        int spA = (int)g_espec[e];
        int iA = (int)pA.x;
        float fA = pA.x - (float)iA;
        float2 tA0 = __half22float2(g_tab0h[iA * 32 + lane]);
        float2 tA1 = __half22float2(g_tab0h[(iA + 1) * 32 + lane]);
        float esA = s0r0;
        esA = (spA == 1) ? s0r1 : esA;
        esA = (spA == 2) ? s0r2 : esA;
        esA = (spA == 3) ? s0r3 : esA;
        esA = (spA == 4) ? s0r4 : esA;
        float w1A = fmaf(fA, tA1.x - tA0.x, tA0.x);
        float w3A = fmaf(fA, tA1.y - tA0.y, tA0.y);
        a0 += w1A * esA;
        float wA = w3A * esA;
        c3x += wA * pA.y; c3y += wA * pA.z; c3z += wA * pA.w;
    }
    g_n0a[n * 32 + lane] = a0;
    g_n1a[(n * 3 + 0) * 32 + lane] = c3x;
    g_n1a[(n * 3 + 1) * 32 + lane] = c3y;
    g_n1a[(n * 3 + 2) * 32 + lane] = c3z;
}

// ---------------- layer0 update: lin2(j<32) + species residual + gate (8 nodes/warp) ----------------
__global__ void __launch_bounds__(256) k_update0(const int* __restrict__ species,
                                                 const float* __restrict__ w_lin2_s,
                                                 const float* __restrict__ w_lin2_v) {
    int w = (blockIdx.x * blockDim.x + threadIdx.x) >> 5;
    int lane = threadIdx.x & 31;
    int base = w * 8;
    if (base >= NN) return;
    float s0[8] = {0}, s1[8] = {0}, vv[8][3] = {{0}};
#pragma unroll 2
    for (int jc = 0; jc < 8; jc++) {
        int j0 = jc * 4;
        float wa[4], wb[4], wc[4];
#pragma unroll
        for (int d = 0; d < 4; d++) {
            wa[d] = w_lin2_s[(j0 + d) * 64 + lane];
            wb[d] = w_lin2_s[(j0 + d) * 64 + 32 + lane];
            wc[d] = w_lin2_v[(j0 + d) * 32 + lane];
        }
#pragma unroll
        for (int g = 0; g < 8; g++) {
            int n = base + g;
            float4 x = *reinterpret_cast<const float4*>(&g_n0a[n * 32 + j0]);
            s0[g] += x.x * wa[0] + x.y * wa[1] + x.z * wa[2] + x.w * wa[3];
            s1[g] += x.x * wb[0] + x.y * wb[1] + x.z * wb[2] + x.w * wb[3];
#pragma unroll
            for (int i = 0; i < 3; i++) {
                float4 xv = *reinterpret_cast<const float4*>(&g_n1a[(n * 3 + i) * 32 + j0]);
                vv[g][i] += xv.x * wc[0] + xv.y * wc[1] + xv.z * wc[2] + xv.w * wc[3];
            }
        }
    }
    const float SC_ = 0.0078125f;
#pragma unroll
    for (int g = 0; g < 8; g++) {
        int n = base + g;
        int sp = species[n];
        float so0 = s0[g] * SC_ + g_s0res[sp * 64 + lane];
        float so1 = s1[g] * SC_ + g_s0res[sp * 64 + 32 + lane];
        float hs = silu(so0);
        float gate = silu(so1);
        g_hs[n * 32 + lane] = hs;
#pragma unroll
        for (int i = 0; i < 3; i++)
            g_hv[(n * 3 + i) * 32 + lane] = vv[g][i] * SC_ * gate;
    }
}

// ---------------- layer1 prep: lin1 + residual (8 nodes/warp, species-sorted) ----------------
__global__ void __launch_bounds__(256) k_prep1(const int* __restrict__ species,
                                               const float* __restrict__ w_res_s,
                                               const float* __restrict__ w_lin1_s,
                                               const float* __restrict__ w_lin1_v) {
    int w = (blockIdx.x * blockDim.x + threadIdx.x) >> 5;
    int lane = threadIdx.x & 31;
    int base = w * 8;
    if (base >= NN) return;
    int nid[8], sp[8];
#pragma unroll
    for (int g = 0; g < 8; g++) { nid[g] = g_nsort[base + g]; sp[g] = species[nid[g]]; }
    bool uni = true;
#pragma unroll
    for (int g = 1; g < 8; g++) uni = uni && (sp[g] == sp[0]);
    const float* Wl1s = w_lin1_s + 1024;
    const float* Wl1v = w_lin1_v + 1024;
    float a_hs[8] = {0}, a_rs0[8] = {0}, a_hv[8][3] = {{0}};
#pragma unroll 2
    for (int uc = 0; uc < 8; uc++) {
        int u0 = uc * 4;
        float ws[4], wv[4], wr0[4];
#pragma unroll
        for (int d = 0; d < 4; d++) {
            ws[d] = Wl1s[(u0 + d) * 32 + lane];
            wv[d] = Wl1v[(u0 + d) * 32 + lane];
        }
        if (uni) {
#pragma unroll
            for (int d = 0; d < 4; d++)
                wr0[d] = w_res_s[(size_t)(((32 + u0 + d) * SC) + sp[0]) * 64 + lane];
        }
#pragma unroll
        for (int g = 0; g < 8; g++) {
            float r0[4];
            if (uni) {
#pragma unroll
                for (int d = 0; d < 4; d++) r0[d] = wr0[d];
            } else {
#pragma unroll
                for (int d = 0; d < 4; d++)
                    r0[d] = w_res_s[(size_t)(((32 + u0 + d) * SC) + sp[g]) * 64 + lane];
            }
            float4 xs = *reinterpret_cast<const float4*>(&g_hs[nid[g] * 32 + u0]);
            float xa[4] = {xs.x, xs.y, xs.z, xs.w};
#pragma unroll
            for (int d = 0; d < 4; d++) {
                a_hs[g] += xa[d] * ws[d];
                a_rs0[g] += xa[d] * r0[d];
            }
#pragma unroll
            for (int i = 0; i < 3; i++) {
                float4 xv = *reinterpret_cast<const float4*>(&g_hv[(nid[g] * 3 + i) * 32 + u0]);
                a_hv[g][i] += xv.x * wv[0] + xv.y * wv[1] + xv.z * wv[2] + xv.w * wv[3];
            }
        }
    }
    const float IS32 = 0.17677669529663687f;
    const float IS160 = 0.07905694150420949f;
#pragma unroll
    for (int g = 0; g < 8; g++) {
        int n = nid[g];
        g_feath[n * 64 + lane * 2] = __floats2half2_rn(a_hs[g] * IS32, a_hv[g][0] * IS32);
        g_feath[n * 64 + lane * 2 + 1] = __floats2half2_rn(a_hv[g][1] * IS32, a_hv[g][2] * IS32);
        g_res1s[n * 32 + lane] = a_rs0[g] * IS160;
    }
}

// ---------------- layer1 gather: fp16 feats + fp16 LUT, (w1,w2) only ----------------
__global__ void __launch_bounds__(256) k_gather1() {
    int n = (blockIdx.x * blockDim.x + threadIdx.x) >> 5;
    int lane = threadIdx.x & 31;
    if (n >= NN) return;
    int e = g_off[n], end = g_off[n + 1];
    float a0 = 0.f, a1 = 0.f;
    for (; e + 1 < end; e += 2) {
        float4 pA = __ldg(&g_epack[e]);
        float4 pB = __ldg(&g_epack[e + 1]);
        int sA = __ldg(&g_esend[e]);
        int sB = __ldg(&g_esend[e + 1]);
        int iA = (int)pA.x, iB = (int)pB.x;
        float fA = pA.x - (float)iA, fB = pB.x - (float)iB;
        float2 tA0 = __half22float2(g_tab1h[iA * 32 + lane]);
        float2 tA1 = __half22float2(g_tab1h[(iA + 1) * 32 + lane]);
        float2 tB0 = __half22float2(g_tab1h[iB * 32 + lane]);
        float2 tB1 = __half22float2(g_tab1h[(iB + 1) * 32 + lane]);
        uint2 rwA = __ldg(reinterpret_cast<const uint2*>(&g_feath[sA * 64 + lane * 2]));
        uint2 rwB = __ldg(reinterpret_cast<const uint2*>(&g_feath[sB * 64 + lane * 2]));
        float2 fA0 = __half22float2(*reinterpret_cast<const __half2*>(&rwA.x));
        float2 fA1 = __half22float2(*reinterpret_cast<const __half2*>(&rwA.y));
        float2 fB0 = __half22float2(*reinterpret_cast<const __half2*>(&rwB.x));
        float2 fB1 = __half22float2(*reinterpret_cast<const __half2*>(&rwB.y));
        float w1A = fmaf(fA, tA1.x - tA0.x, tA0.x);
        float w2A = fmaf(fA, tA1.y - tA0.y, tA0.y);
        float w1B = fmaf(fB, tB1.x - tB0.x, tB0.x);
        float w2B = fmaf(fB, tB1.y - tB0.y, tB0.y);
        a0 += w1A * fA0.x + w1B * fB0.x;
        float dA = fA0.y * pA.y + fA1.x * pA.z + fA1.y * pA.w;
        float dB = fB0.y * pB.y + fB1.x * pB.z + fB1.y * pB.w;
        a1 += w2A * dA + w2B * dB;
    }
    if (e < end) {
        float4 pA = __ldg(&g_epack[e]);
        int sA = __ldg(&g_esend[e]);
        int iA = (int)pA.x;
        float fA = pA.x - (float)iA;
        float2 tA0 = __half22float2(g_tab1h[iA * 32 + lane]);
        float2 tA1 = __half22float2(g_tab1h[(iA + 1) * 32 + lane]);
        uint2 rwA = __ldg(reinterpret_cast<const uint2*>(&g_feath[sA * 64 + lane * 2]));
        float2 fA0 = __half22float2(*reinterpret_cast<const __half2*>(&rwA.x));
        float2 fA1 = __half22float2(*reinterpret_cast<const __half2*>(&rwA.y));
        float w1A = fmaf(fA, tA1.x - tA0.x, tA0.x);
        float w2A = fmaf(fA, tA1.y - tA0.y, tA0.y);
        a0 += w1A * fA0.x;
        a1 += w2A * (fA0.y * pA.y + fA1.x * pA.z + fA1.y * pA.w);
    }
    g_n0b[n * 64 + lane] = a0;
    g_n0b[n * 64 + 32 + lane] = a1 * 0.5773502691896258f;
}

// ---------------- layer1 update + readout (8 nodes/warp) ----------------
__global__ void __launch_bounds__(256) k_update1(const float* __restrict__ w_lin2_s,
                                                 const float* __restrict__ w_out1,
                                                 const float* __restrict__ w_out2,
                                                 float* __restrict__ out) {
    int w = (blockIdx.x * blockDim.x + threadIdx.x) >> 5;
    int lane = threadIdx.x & 31;
    int base = w * 8;
    if (base >= NN) return;
    const float* W2s = w_lin2_s + 4096;
    float s0[8] = {0};
#pragma unroll 4
    for (int jc = 0; jc < 16; jc++) {
        int j0 = jc * 4;
        float wa[4];
#pragma unroll
        for (int d = 0; d < 4; d++) wa[d] = W2s[(j0 + d) * 64 + lane];
#pragma unroll
        for (int g = 0; g < 8; g++) {
            float4 x = *reinterpret_cast<const float4*>(&g_n0b[(base + g) * 64 + j0]);
            s0[g] += x.x * wa[0] + x.y * wa[1] + x.z * wa[2] + x.w * wa[3];
        }
    }
    float wcomb = 0.f;
#pragma unroll
    for (int k = 0; k < 16; k++) wcomb += w_out1[lane * 16 + k] * w_out2[k];
    const float SC_ = 0.0078125f;
#pragma unroll
    for (int g = 0; g < 8; g++) {
        int n = base + g;
        float hs = silu(s0[g] * SC_ + g_res1s[n * 32 + lane]);
        float z = hs * wcomb;
        z += __shfl_xor_sync(0xffffffffu, z, 16);
        z += __shfl_xor_sync(0xffffffffu, z, 8);
        z += __shfl_xor_sync(0xffffffffu, z, 4);
        z += __shfl_xor_sync(0xffffffffu, z, 2);
        z += __shfl_xor_sync(0xffffffffu, z, 1);
        if (lane == 0) out[n] = z * (0.17677669529663687f * 0.25f);
    }
}

// ---------------- launch ----------------
extern "C" void kernel_launch(void* const* d_in, const int* in_sizes, int n_in,
                              void* d_out, int out_size) {
    const float* edge_vectors = (const float*)d_in[0];
    const int* species        = (const int*)d_in[1];
    const int* senders        = (const int*)d_in[2];
    const int* receivers      = (const int*)d_in[3];
    const float* embed_w      = (const float*)d_in[4];
    const float* w_res_s      = (const float*)d_in[5];
    const float* w_lin1_s     = (const float*)d_in[7];
    const float* w_lin1_v     = (const float*)d_in[8];
    const float* mlp_w0       = (const float*)d_in[9];
    const float* mlp_w1       = (const float*)d_in[10];
    const float* mlp_w2       = (const float*)d_in[11];
    const float* w_lin2_s     = (const float*)d_in[12];
    const float* w_lin2_v     = (const float*)d_in[13];
    const float* w_out1       = (const float*)d_in[14];
    const float* w_out2       = (const float*)d_in[15];
    float* out = (float*)d_out;

    const int EB256 = (EE + 255) / 256;
    const int GPB = (NN + 7) / 8;
    const int WPB8 = (NN / 8 + 7) / 8;

    k_zero<<<(NN + 255) / 256, 256>>>();
    k_hist<<<EB256, 256>>>(edge_vectors, receivers, species);
    k_scan1<<<49, 1024>>>();
    k_scan2<<<1, 32>>>();
    k_scan3<<<49, 1024>>>();
    k_scatter<<<EB256, 256>>>(edge_vectors, senders, receivers, species);
    k_build_table<<<dim3(TBINS, 2), 128>>>(mlp_w0, mlp_w1, mlp_w2);
    k_spec0<<<1, 160>>>(embed_w, w_lin1_s, w_res_s);

    // layer 0
    k_gather0<<<GPB, 256>>>();
    k_update0<<<WPB8, 256>>>(species, w_lin2_s, w_lin2_v);

    // layer 1
    k_prep1<<<WPB8, 256>>>(species, w_res_s, w_lin1_s, w_lin1_v);
    k_gather1<<<GPB, 256>>>();
    k_update1<<<WPB8, 256>>>(w_lin2_s, w_out1, w_out2, out);
}

// round 8
// speedup vs baseline: 5.8778x; 1.0171x over previous
#include <cuda_runtime.h>
#include <cuda_fp16.h>

#define NN 50000
#define EE 800000
#define SC 5
#define NBC 8
#define HC 64
#define NWC 128
#define TBINS 2048
#define RMAXF 5.0f

#define NODE_BLOCKS 196         // 196*256 >= NN

// ---------------- device scratch ----------------
__device__ int g_zb[NN + 16];            // [0,NN): degree->cursor; [NN,NN+5): species counts
__device__ int g_off[NN + 1];
__device__ int g_part[NODE_BLOCKS];
__device__ int g_scur[SC];
__device__ int g_nsort[NN];
__device__ uint4 g_erec[EE];             // packed CSR edge record: p | sh01 | (spec<<16|sh2) | sender
__device__ float g_hs[NN * 32];
__device__ float g_hv[NN * 96];
__device__ __half2 g_feath[NN * 64];     // layer1 feats: (es,ev0),(ev1,ev2)
__device__ float g_res1s[NN * 32];
__device__ float g_n0a[NN * 32];
__device__ float g_n1a[NN * 96];
__device__ float g_n0b[NN * 64];
__device__ __half2 g_tab0h[TBINS * 32];  // layer0 LUT (w1, w3)
__device__ __half2 g_tab1h[TBINS * 32];  // layer1 LUT (w1, w2)
__device__ float g_s0hsl[SC * 32];
__device__ float g_s0res[SC * 64];

__device__ __forceinline__ float silu(float x) { return x / (1.0f + __expf(-x)); }

// ---------------- hist: degree + species counts ----------------
__global__ void k_hist(const float* __restrict__ evec, const int* __restrict__ recv,
                       const int* __restrict__ species) {
    int e = blockIdx.x * blockDim.x + threadIdx.x;
    if (e < NN) atomicAdd(&g_zb[NN + species[e]], 1);
    if (e >= EE) return;
    float x = evec[e * 3], y = evec[e * 3 + 1], z = evec[e * 3 + 2];
    if (x * x + y * y + z * z < RMAXF * RMAXF) atomicAdd(&g_zb[recv[e]], 1);
}

// ---------------- scanA: block-local scan + species prefix ----------------
__global__ void k_scanA() {
    __shared__ int ws[8];
    int b = blockIdx.x, t = threadIdx.x;
    int lane = t & 31, wid = t >> 5;
    int idx = b * 256 + t;
    int v = (idx < NN) ? g_zb[idx] : 0;
    int x = v;
#pragma unroll
    for (int d = 1; d < 32; d <<= 1) {
        int y = __shfl_up_sync(0xffffffffu, x, d);
        if (lane >= d) x += y;
    }
    if (lane == 31) ws[wid] = x;
    __syncthreads();
    if (wid == 0 && lane < 8) {
        int s = ws[lane];
#pragma unroll
        for (int d = 1; d < 8; d <<= 1) {
            int y = __shfl_up_sync(0xffu, s, d);
            if (lane >= d) s += y;
        }
        ws[lane] = s;
    }
    __syncthreads();
    int incl = x + (wid > 0 ? ws[wid - 1] : 0);
    if (idx < NN) g_off[idx] = incl - v;   // block-local exclusive
    if (t == 255) g_part[b] = incl;
    if (b == 0 && t == 0) {                // species prefix (hist complete)
        int a2 = 0;
        for (int s = 0; s < SC; s++) { g_scur[s] = a2; a2 += g_zb[NN + s]; }
    }
}

// ---------------- scanB: add block offsets + init cursors ----------------
__global__ void k_scanB() {
    __shared__ int myoff;
    int b = blockIdx.x, t = threadIdx.x;
    int lane = t & 31, wid = t >> 5;
    if (wid == 0) {
        int s = 0;
        for (int j = lane; j < b; j += 32) s += g_part[j];
#pragma unroll
        for (int d = 16; d > 0; d >>= 1) s += __shfl_xor_sync(0xffffffffu, s, d);
        if (lane == 0) myoff = s;
    }
    __syncthreads();
    int idx = b * 256 + t;
    if (idx < NN) {
        int o = g_off[idx] + myoff;
        g_off[idx] = o;
        g_zb[idx] = o;   // cursor for scatter
    }
    if (b == 0 && t == 0) {
        int tot = 0;
        for (int j = 0; j < NODE_BLOCKS; j++) tot += g_part[j];
        g_off[NN] = tot;
    }
}

// ---------------- scatter: packed 16B record + species-sorted node list ----------------
__global__ void k_scatter(const float* __restrict__ evec, const int* __restrict__ senders,
                          const int* __restrict__ recv, const int* __restrict__ species) {
    int e = blockIdx.x * blockDim.x + threadIdx.x;
    if (e < NN) {
        int pos = atomicAdd(&g_scur[species[e]], 1);
        g_nsort[pos] = e;
    }
    if (e >= EE) return;
    float x = evec[e * 3], y = evec[e * 3 + 1], z = evec[e * 3 + 2];
    float r2 = x * x + y * y + z * z;
    if (r2 >= RMAXF * RMAXF) return;
    float r = sqrtf(r2 + 1e-12f);
    float ir = 1.0f / r;
    const float SQ3 = 1.7320508075688772f;
    int s = senders[e];
    int pos = atomicAdd(&g_zb[recv[e]], 1);
    uint4 rec;
    rec.x = __float_as_uint(r * ((float)(TBINS - 1) / RMAXF));
    __half2 h01 = __floats2half2_rn(SQ3 * x * ir, SQ3 * y * ir);
    rec.y = *reinterpret_cast<unsigned int*>(&h01);
    __half h2 = __float2half_rn(SQ3 * z * ir);
    rec.z = ((unsigned int)species[s] << 16) | (unsigned int)__half_as_ushort(h2);
    rec.w = (unsigned int)s;
    g_erec[pos] = rec;
}

// ---------------- radial-MLP LUT (fp16 rows, both layers) ----------------
__global__ void k_build_table(const float* __restrict__ mlp_w0,
                              const float* __restrict__ mlp_w1,
                              const float* __restrict__ mlp_w2) {
    __shared__ float a1[HC];
    __shared__ float a2[HC];
    __shared__ float eemb[NBC];
    __shared__ float sacc[128];
    int bin = blockIdx.x;
    int l = blockIdx.y;
    int tid = threadIdx.x;
    const float* w0 = mlp_w0 + l * NBC * HC;
    const float* w1 = mlp_w1 + l * HC * HC;
    const float* w2 = mlp_w2 + l * HC * NWC;
    if (tid < NBC) {
        float r = (float)bin * (RMAXF / (float)(TBINS - 1));
        float rs = fmaxf(r, 1e-6f);
        float ir = 1.0f / rs;
        float xr = rs * (1.0f / RMAXF);
        float x3 = xr * xr * xr, x6 = x3 * x3, x7 = x6 * xr, x8 = x7 * xr;
        float env = 1.0f - 28.0f * x6 + 48.0f * x7 - 21.0f * x8;
        const float PI_ = 3.14159265358979323846f;
        eemb[tid] = 0.6324555320336759f * ir * env * sinf(PI_ * xr * (float)(tid + 1));
    }
    __syncthreads();
    if (tid < HC) {
        float acc = 0.f;
#pragma unroll
        for (int k = 0; k < NBC; k++) acc += eemb[k] * w0[k * HC + tid];
        a1[tid] = silu(acc * 0.35355339059327373f);
    }
    __syncthreads();
    if (tid < HC) {
        float acc = 0.f;
#pragma unroll 8
        for (int k = 0; k < HC; k++) acc += a1[k] * w1[k * HC + tid];
        a2[tid] = silu(acc * 0.125f);
    }
    __syncthreads();
    {
        float acc = 0.f;
#pragma unroll 8
        for (int k = 0; k < HC; k++) acc += a2[k] * w2[k * NWC + tid];
        sacc[tid] = acc;
    }
    __syncthreads();
    if (tid < 32) {
        if (l == 0)
            g_tab0h[bin * 32 + tid] = __floats2half2_rn(sacc[tid], sacc[64 + tid]);
        else
            g_tab1h[bin * 32 + tid] = __floats2half2_rn(sacc[tid], sacc[32 + tid]);
    }
}

// ---------------- layer0 species-pure node prep ----------------
__global__ void k_spec0(const float* __restrict__ embed_w,
                        const float* __restrict__ w_lin1_s,
                        const float* __restrict__ w_res_s) {
    int w = threadIdx.x >> 5, lane = threadIdx.x & 31;
    if (w >= SC) return;
    float a_hs = 0.f, a_rs0 = 0.f, a_rs1 = 0.f;
#pragma unroll 4
    for (int u = 0; u < 32; u++) {
        float x = embed_w[w * 32 + u] * 0.4472135954999579f;
        a_hs += x * w_lin1_s[u * 32 + lane];
        const float* rs = w_res_s + (size_t)(u * SC + w) * 64;
        a_rs0 += x * rs[lane];
        a_rs1 += x * rs[32 + lane];
    }
    g_s0hsl[w * 32 + lane] = a_hs * 0.17677669529663687f;
    g_s0res[w * 64 + lane] = a_rs0 * 0.07905694150420949f;
    g_s0res[w * 64 + 32 + lane] = a_rs1 * 0.07905694150420949f;
}

// ---------------- layer0 gather: 1 record load + 2 table rows per edge ----------------
__global__ void __launch_bounds__(128) k_gather0() {
    int n = (blockIdx.x * blockDim.x + threadIdx.x) >> 5;
    int lane = threadIdx.x & 31;
    if (n >= NN) return;
    float s0r0 = g_s0hsl[lane];
    float s0r1 = g_s0hsl[32 + lane];
    float s0r2 = g_s0hsl[64 + lane];
    float s0r3 = g_s0hsl[96 + lane];
    float s0r4 = g_s0hsl[128 + lane];
    int e = g_off[n], end = g_off[n + 1];
    float a0 = 0.f, c3x = 0.f, c3y = 0.f, c3z = 0.f;
    for (; e + 1 < end; e += 2) {
        uint4 rA = __ldg(&g_erec[e]);
        uint4 rB = __ldg(&g_erec[e + 1]);
        float pA = __uint_as_float(rA.x), pB = __uint_as_float(rB.x);
        int iA = (int)pA, iB = (int)pB;
        float fA = pA - (float)iA, fB = pB - (float)iB;
        float2 tA0 = __half22float2(g_tab0h[iA * 32 + lane]);
        float2 tA1 = __half22float2(g_tab0h[(iA + 1) * 32 + lane]);
        float2 tB0 = __half22float2(g_tab0h[iB * 32 + lane]);
        float2 tB1 = __half22float2(g_tab0h[(iB + 1) * 32 + lane]);
        float2 shA = __half22float2(*reinterpret_cast<const __half2*>(&rA.y));
        float2 shB = __half22float2(*reinterpret_cast<const __half2*>(&rB.y));
        float sh2A = __half2float(__ushort_as_half((unsigned short)(rA.z & 0xffffu)));
        float sh2B = __half2float(__ushort_as_half((unsigned short)(rB.z & 0xffffu)));
        int spA = rA.z >> 16, spB = rB.z >> 16;
        float esA = s0r0;
        esA = (spA == 1) ? s0r1 : esA;
        esA = (spA == 2) ? s0r2 : esA;
        esA = (spA == 3) ? s0r3 : esA;
        esA = (spA == 4) ? s0r4 : esA;
        float esB = s0r0;
        esB = (spB == 1) ? s0r1 : esB;
        esB = (spB == 2) ? s0r2 : esB;
        esB = (spB == 3) ? s0r3 : esB;
        esB = (spB == 4) ? s0r4 : esB;
        float w1A = fmaf(fA, tA1.x - tA0.x, tA0.x);
        float w3A = fmaf(fA, tA1.y - tA0.y, tA0.y);
        float w1B = fmaf(fB, tB1.x - tB0.x, tB0.x);
        float w3B = fmaf(fB, tB1.y - tB0.y, tB0.y);
        a0 += w1A * esA + w1B * esB;
        float wA = w3A * esA, wB = w3B * esB;
        c3x += wA * shA.x + wB * shB.x;
        c3y += wA * shA.y + wB * shB.y;
        c3z += wA * sh2A + wB * sh2B;
    }
    if (e < end) {
        uint4 rA = __ldg(&g_erec[e]);
        float pA = __uint_as_float(rA.x);
        int iA = (int)pA;
        float fA = pA - (float)iA;
        float2 tA0 = __half22float2(g_tab0h[iA * 32 + lane]);
        float2 tA1 = __half22float2(g_tab0h[(iA + 1) * 32 + lane]);
        float2 shA = __half22float2(*reinterpret_cast<const __half2*>(&rA.y));
        float sh2A = __half2float(__ushort_as_half((unsigned short)(rA.z & 0xffffu)));
        int spA = rA.z >> 16;
        float esA = s0r0;
        esA = (spA == 1) ? s0r1 : esA;
        esA = (spA == 2) ? s0r2 : esA;
        esA = (spA == 3) ? s0r3 : esA;
        esA = (spA == 4) ? s0r4 : esA;
        float w1A = fmaf(fA, tA1.x - tA0.x, tA0.x);
        float w3A = fmaf(fA, tA1.y - tA0.y, tA0.y);
        a0 += w1A * esA;
        float wA = w3A * esA;
        c3x += wA * shA.x; c3y += wA * shA.y; c3z += wA * sh2A;
    }
    g_n0a[n * 32 + lane] = a0;
    g_n1a[(n * 3 + 0) * 32 + lane] = c3x;
    g_n1a[(n * 3 + 1) * 32 + lane] = c3y;
    g_n1a[(n * 3 + 2) * 32 + lane] = c3z;
}

// ---------------- layer0 update ----------------
__global__ void __launch_bounds__(256) k_update0(const int* __restrict__ species,
                                                 const float* __restrict__ w_lin2_s,
                                                 const float* __restrict__ w_lin2_v) {
    int w = (blockIdx.x * blockDim.x + threadIdx.x) >> 5;
    int lane = threadIdx.x & 31;
    int base = w * 8;
    if (base >= NN) return;
    float s0[8] = {0}, s1[8] = {0}, vv[8][3] = {{0}};
#pragma unroll 2
    for (int jc = 0; jc < 8; jc++) {
        int j0 = jc * 4;
        float wa[4], wb[4], wc[4];
#pragma unroll
        for (int d = 0; d < 4; d++) {
            wa[d] = w_lin2_s[(j0 + d) * 64 + lane];
            wb[d] = w_lin2_s[(j0 + d) * 64 + 32 + lane];
            wc[d] = w_lin2_v[(j0 + d) * 32 + lane];
        }
#pragma unroll
        for (int g = 0; g < 8; g++) {
            int n = base + g;
            float4 x = *reinterpret_cast<const float4*>(&g_n0a[n * 32 + j0]);
            s0[g] += x.x * wa[0] + x.y * wa[1] + x.z * wa[2] + x.w * wa[3];
            s1[g] += x.x * wb[0] + x.y * wb[1] + x.z * wb[2] + x.w * wb[3];
#pragma unroll
            for (int i = 0; i < 3; i++) {
                float4 xv = *reinterpret_cast<const float4*>(&g_n1a[(n * 3 + i) * 32 + j0]);
                vv[g][i] += xv.x * wc[0] + xv.y * wc[1] + xv.z * wc[2] + xv.w * wc[3];
            }
        }
    }
    const float SC_ = 0.0078125f;
#pragma unroll
    for (int g = 0; g < 8; g++) {
        int n = base + g;
        int sp = species[n];
        float so0 = s0[g] * SC_ + g_s0res[sp * 64 + lane];
        float so1 = s1[g] * SC_ + g_s0res[sp * 64 + 32 + lane];
        float hs = silu(so0);
        float gate = silu(so1);
        g_hs[n * 32 + lane] = hs;
#pragma unroll
        for (int i = 0; i < 3; i++)
            g_hv[(n * 3 + i) * 32 + lane] = vv[g][i] * SC_ * gate;
    }
}

// ---------------- layer1 prep ----------------
__global__ void __launch_bounds__(256) k_prep1(const int* __restrict__ species,
                                               const float* __restrict__ w_res_s,
                                               const float* __restrict__ w_lin1_s,
                                               const float* __restrict__ w_lin1_v) {
    int w = (blockIdx.x * blockDim.x + threadIdx.x) >> 5;
    int lane = threadIdx.x & 31;
    int base = w * 8;
    if (base >= NN) return;
    int nid[8], sp[8];
#pragma unroll
    for (int g = 0; g < 8; g++) { nid[g] = g_nsort[base + g]; sp[g] = species[nid[g]]; }
    bool uni = true;
#pragma unroll
    for (int g = 1; g < 8; g++) uni = uni && (sp[g] == sp[0]);
    const float* Wl1s = w_lin1_s + 1024;
    const float* Wl1v = w_lin1_v + 1024;
    float a_hs[8] = {0}, a_rs0[8] = {0}, a_hv[8][3] = {{0}};
#pragma unroll 2
    for (int uc = 0; uc < 8; uc++) {
        int u0 = uc * 4;
        float ws[4], wv[4], wr0[4];
#pragma unroll
        for (int d = 0; d < 4; d++) {
            ws[d] = Wl1s[(u0 + d) * 32 + lane];
            wv[d] = Wl1v[(u0 + d) * 32 + lane];
        }
        if (uni) {
#pragma unroll
            for (int d = 0; d < 4; d++)
                wr0[d] = w_res_s[(size_t)(((32 + u0 + d) * SC) + sp[0]) * 64 + lane];
        }
#pragma unroll
        for (int g = 0; g < 8; g++) {
            float r0[4];
            if (uni) {
#pragma unroll
                for (int d = 0; d < 4; d++) r0[d] = wr0[d];
            } else {
#pragma unroll
                for (int d = 0; d < 4; d++)
                    r0[d] = w_res_s[(size_t)(((32 + u0 + d) * SC) + sp[g]) * 64 + lane];
            }
            float4 xs = *reinterpret_cast<const float4*>(&g_hs[nid[g] * 32 + u0]);
            float xa[4] = {xs.x, xs.y, xs.z, xs.w};
#pragma unroll
            for (int d = 0; d < 4; d++) {
                a_hs[g] += xa[d] * ws[d];
                a_rs0[g] += xa[d] * r0[d];
            }
#pragma unroll
            for (int i = 0; i < 3; i++) {
                float4 xv = *reinterpret_cast<const float4*>(&g_hv[(nid[g] * 3 + i) * 32 + u0]);
                a_hv[g][i] += xv.x * wv[0] + xv.y * wv[1] + xv.z * wv[2] + xv.w * wv[3];
            }
        }
    }
    const float IS32 = 0.17677669529663687f;
    const float IS160 = 0.07905694150420949f;
#pragma unroll
    for (int g = 0; g < 8; g++) {
        int n = nid[g];
        g_feath[n * 64 + lane * 2] = __floats2half2_rn(a_hs[g] * IS32, a_hv[g][0] * IS32);
        g_feath[n * 64 + lane * 2 + 1] = __floats2half2_rn(a_hv[g][1] * IS32, a_hv[g][2] * IS32);
        g_res1s[n * 32 + lane] = a_rs0[g] * IS160;
    }
}

// ---------------- layer1 gather ----------------
__global__ void __launch_bounds__(128) k_gather1() {
    int n = (blockIdx.x * blockDim.x + threadIdx.x) >> 5;
    int lane = threadIdx.x & 31;
    if (n >= NN) return;
    int e = g_off[n], end = g_off[n + 1];
    float a0 = 0.f, a1 = 0.f;
    for (; e + 1 < end; e += 2) {
        uint4 rA = __ldg(&g_erec[e]);
        uint4 rB = __ldg(&g_erec[e + 1]);
        float pA = __uint_as_float(rA.x), pB = __uint_as_float(rB.x);
        int iA = (int)pA, iB = (int)pB;
        float fA = pA - (float)iA, fB = pB - (float)iB;
        float2 tA0 = __half22float2(g_tab1h[iA * 32 + lane]);
        float2 tA1 = __half22float2(g_tab1h[(iA + 1) * 32 + lane]);
        float2 tB0 = __half22float2(g_tab1h[iB * 32 + lane]);
        float2 tB1 = __half22float2(g_tab1h[(iB + 1) * 32 + lane]);
        uint2 fwA = __ldg(reinterpret_cast<const uint2*>(&g_feath[(int)rA.w * 64 + lane * 2]));
        uint2 fwB = __ldg(reinterpret_cast<const uint2*>(&g_feath[(int)rB.w * 64 + lane * 2]));
        float2 fA0 = __half22float2(*reinterpret_cast<const __half2*>(&fwA.x));
        float2 fA1 = __half22float2(*reinterpret_cast<const __half2*>(&fwA.y));
        float2 fB0 = __half22float2(*reinterpret_cast<const __half2*>(&fwB.x));
        float2 fB1 = __half22float2(*reinterpret_cast<const __half2*>(&fwB.y));
        float2 shA = __half22float2(*reinterpret_cast<const __half2*>(&rA.y));
        float2 shB = __half22float2(*reinterpret_cast<const __half2*>(&rB.y));
        float sh2A = __half2float(__ushort_as_half((unsigned short)(rA.z & 0xffffu)));
        float sh2B = __half2float(__ushort_as_half((unsigned short)(rB.z & 0xffffu)));
        float w1A = fmaf(fA, tA1.x - tA0.x, tA0.x);
        float w2A = fmaf(fA, tA1.y - tA0.y, tA0.y);
        float w1B = fmaf(fB, tB1.x - tB0.x, tB0.x);
        float w2B = fmaf(fB, tB1.y - tB0.y, tB0.y);
        a0 += w1A * fA0.x + w1B * fB0.x;
        float dA = fA0.y * shA.x + fA1.x * shA.y + fA1.y * sh2A;
        float dB = fB0.y * shB.x + fB1.x * shB.y + fB1.y * sh2B;
        a1 += w2A * dA + w2B * dB;
    }
    if (e < end) {
        uint4 rA = __ldg(&g_erec[e]);
        float pA = __uint_as_float(rA.x);
        int iA = (int)pA;
        float fA = pA - (float)iA;
        float2 tA0 = __half22float2(g_tab1h[iA * 32 + lane]);
        float2 tA1 = __half22float2(g_tab1h[(iA + 1) * 32 + lane]);
        uint2 fwA = __ldg(reinterpret_cast<const uint2*>(&g_feath[(int)rA.w * 64 + lane * 2]));
        float2 fA0 = __half22float2(*reinterpret_cast<const __half2*>(&fwA.x));
        float2 fA1 = __half22float2(*reinterpret_cast<const __half2*>(&fwA.y));
        float2 shA = __half22float2(*reinterpret_cast<const __half2*>(&rA.y));
        float sh2A = __half2float(__ushort_as_half((unsigned short)(rA.z & 0xffffu)));
        float w1A = fmaf(fA, tA1.x - tA0.x, tA0.x);
        float w2A = fmaf(fA, tA1.y - tA0.y, tA0.y);
        a0 += w1A * fA0.x;
        a1 += w2A * (fA0.y * shA.x + fA1.x * shA.y + fA1.y * sh2A);
    }
    g_n0b[n * 64 + lane] = a0;
    g_n0b[n * 64 + 32 + lane] = a1 * 0.5773502691896258f;
}

// ---------------- layer1 update + readout ----------------
__global__ void __launch_bounds__(256) k_update1(const float* __restrict__ w_lin2_s,
                                                 const float* __restrict__ w_out1,
                                                 const float* __restrict__ w_out2,
                                                 float* __restrict__ out) {
    int w = (blockIdx.x * blockDim.x + threadIdx.x) >> 5;
    int lane = threadIdx.x & 31;
    int base = w * 8;
    if (base >= NN) return;
    const float* W2s = w_lin2_s + 4096;
    float s0[8] = {0};
#pragma unroll 4
    for (int jc = 0; jc < 16; jc++) {
        int j0 = jc * 4;
        float wa[4];
#pragma unroll
        for (int d = 0; d < 4; d++) wa[d] = W2s[(j0 + d) * 64 + lane];
#pragma unroll
        for (int g = 0; g < 8; g++) {
            float4 x = *reinterpret_cast<const float4*>(&g_n0b[(base + g) * 64 + j0]);
            s0[g] += x.x * wa[0] + x.y * wa[1] + x.z * wa[2] + x.w * wa[3];
        }
    }
    float wcomb = 0.f;
#pragma unroll
    for (int k = 0; k < 16; k++) wcomb += w_out1[lane * 16 + k] * w_out2[k];
    const float SC_ = 0.0078125f;
#pragma unroll
    for (int g = 0; g < 8; g++) {
        int n = base + g;
        float hs = silu(s0[g] * SC_ + g_res1s[n * 32 + lane]);
        float z = hs * wcomb;
        z += __shfl_xor_sync(0xffffffffu, z, 16);
        z += __shfl_xor_sync(0xffffffffu, z, 8);
        z += __shfl_xor_sync(0xffffffffu, z, 4);
        z += __shfl_xor_sync(0xffffffffu, z, 2);
        z += __shfl_xor_sync(0xffffffffu, z, 1);
        if (lane == 0) out[n] = z * (0.17677669529663687f * 0.25f);
    }
}

// ---------------- launch ----------------
extern "C" void kernel_launch(void* const* d_in, const int* in_sizes, int n_in,
                              void* d_out, int out_size) {
    const float* edge_vectors = (const float*)d_in[0];
    const int* species        = (const int*)d_in[1];
    const int* senders        = (const int*)d_in[2];
    const int* receivers      = (const int*)d_in[3];
    const float* embed_w      = (const float*)d_in[4];
    const float* w_res_s      = (const float*)d_in[5];
    const float* w_lin1_s     = (const float*)d_in[7];
    const float* w_lin1_v     = (const float*)d_in[8];
    const float* mlp_w0       = (const float*)d_in[9];
    const float* mlp_w1       = (const float*)d_in[10];
    const float* mlp_w2       = (const float*)d_in[11];
    const float* w_lin2_s     = (const float*)d_in[12];
    const float* w_lin2_v     = (const float*)d_in[13];
    const float* w_out1       = (const float*)d_in[14];
    const float* w_out2       = (const float*)d_in[15];
    float* out = (float*)d_out;

    void* zb_ptr = nullptr;
    cudaGetSymbolAddress(&zb_ptr, g_zb);
    cudaMemsetAsync(zb_ptr, 0, (NN + 16) * sizeof(int));

    const int EB256 = (EE + 255) / 256;
    const int GPB = (NN + 3) / 4;          // gather: 128-thr blocks, warp per node
    const int WPB8 = (NN / 8 + 7) / 8;     // 8-node-per-warp node kernels

    k_hist<<<EB256, 256>>>(edge_vectors, receivers, species);
    k_build_table<<<dim3(TBINS, 2), 128>>>(mlp_w0, mlp_w1, mlp_w2);
    k_spec0<<<1, 160>>>(embed_w, w_lin1_s, w_res_s);
    k_scanA<<<NODE_BLOCKS, 256>>>();
    k_scanB<<<NODE_BLOCKS, 256>>>();
    k_scatter<<<EB256, 256>>>(edge_vectors, senders, receivers, species);

    // layer 0
    k_gather0<<<GPB, 128>>>();
    k_update0<<<WPB8, 256>>>(species, w_lin2_s, w_lin2_v);

    // layer 1
    k_prep1<<<WPB8, 256>>>(species, w_res_s, w_lin1_s, w_lin1_v);
    k_gather1<<<GPB, 128>>>();
    k_update1<<<WPB8, 256>>>(w_lin2_s, w_out1, w_out2, out);
}

// round 9
// speedup vs baseline: 6.9576x; 1.1837x over previous
#include <cuda_runtime.h>
#include <cuda_fp16.h>

#define NN 50000
#define EE 800000
#define SC 5
#define NBC 8
#define HC 64
#define NWC 128
#define TBINS 2048
#define RMAXF 5.0f

#define NODE_BLOCKS 196         // 196*256 >= NN

// ---------------- device scratch ----------------
// g_zb layout: [0,NN) degree->cursor; [NN,NN+5) species counts; [NN+16, NN+16+NODE_BLOCKS) lookback states
__device__ int g_zb[NN + 16 + NODE_BLOCKS];
__device__ int g_off[NN + 1];
__device__ int g_scur[SC];
__device__ int g_nsort[NN];
__device__ uint4 g_erec[EE];             // packed CSR edge record: p | sh01 | (spec<<16|sh2) | sender
__device__ float g_hs[NN * 32];
__device__ float g_hv[NN * 96];
__device__ __half2 g_feath[NN * 64];     // layer1 feats: (es,ev0),(ev1,ev2)
__device__ float g_res1s[NN * 32];
__device__ __half2 g_tab0h[TBINS * 32];  // layer0 LUT (w1, w3)
__device__ __half2 g_tab1h[TBINS * 32];  // layer1 LUT (w1, w2)
__device__ float g_s0hsl[SC * 32];
__device__ float g_s0res[SC * 64];
__device__ float g_wcomb[32];            // readout combined weights

__device__ __forceinline__ float silu(float x) { return x / (1.0f + __expf(-x)); }

// ---------------- hist: degree + species counts ----------------
__global__ void k_hist(const float* __restrict__ evec, const int* __restrict__ recv,
                       const int* __restrict__ species) {
    int e = blockIdx.x * blockDim.x + threadIdx.x;
    if (e < NN) atomicAdd(&g_zb[NN + species[e]], 1);
    if (e >= EE) return;
    float x = evec[e * 3], y = evec[e * 3 + 1], z = evec[e * 3 + 2];
    if (x * x + y * y + z * z < RMAXF * RMAXF) atomicAdd(&g_zb[recv[e]], 1);
}

// ---------------- single-pass scan with decoupled lookback ----------------
#define FLAGP 0x40000000u
#define FLAGX 0x80000000u
#define VALM  0x3FFFFFFFu

__global__ void __launch_bounds__(256) k_scan() {
    __shared__ int ws[8];
    __shared__ int s_tot, s_off;
    int b = blockIdx.x, t = threadIdx.x;
    int lane = t & 31, wid = t >> 5;
    int idx = b * 256 + t;
    int v = (idx < NN) ? g_zb[idx] : 0;
    int x = v;
#pragma unroll
    for (int d = 1; d < 32; d <<= 1) {
        int y = __shfl_up_sync(0xffffffffu, x, d);
        if (lane >= d) x += y;
    }
    if (lane == 31) ws[wid] = x;
    __syncthreads();
    if (wid == 0 && lane < 8) {
        int s = ws[lane];
#pragma unroll
        for (int d = 1; d < 8; d <<= 1) {
            int y = __shfl_up_sync(0xffu, s, d);
            if (lane >= d) s += y;
        }
        ws[lane] = s;
    }
    __syncthreads();
    int incl = x + (wid > 0 ? ws[wid - 1] : 0);
    if (t == 255) s_tot = incl;
    __syncthreads();
    unsigned int* look = reinterpret_cast<unsigned int*>(&g_zb[NN + 16]);
    if (t == 0) {
        if (b == 0) {
            int a2 = 0;   // species prefix (hist done)
            for (int s = 0; s < SC; s++) { g_scur[s] = a2; a2 += g_zb[NN + s]; }
            s_off = 0;
            atomicExch(&look[0], (unsigned)s_tot | FLAGX);
        } else {
            atomicExch(&look[b], (unsigned)s_tot | FLAGP);
            int run = 0, j = b - 1;
            while (true) {
                unsigned st;
                while ((((st = atomicAdd(&look[j], 0u))) & (FLAGP | FLAGX)) == 0u)
                    __nanosleep(32);
                run += (int)(st & VALM);
                if (st & FLAGX) break;
                j--;
            }
            s_off = run;
            atomicExch(&look[b], (unsigned)(run + s_tot) | FLAGX);
        }
        if (b == NODE_BLOCKS - 1) g_off[NN] = s_off + s_tot;
    }
    __syncthreads();
    if (idx < NN) {
        int o = incl - v + s_off;
        g_off[idx] = o;
        g_zb[idx] = o;   // cursor for scatter
    }
}

// ---------------- scatter: packed 16B record + species-sorted node list ----------------
__global__ void k_scatter(const float* __restrict__ evec, const int* __restrict__ senders,
                          const int* __restrict__ recv, const int* __restrict__ species) {
    int e = blockIdx.x * blockDim.x + threadIdx.x;
    if (e < NN) {
        int pos = atomicAdd(&g_scur[species[e]], 1);
        g_nsort[pos] = e;
    }
    if (e >= EE) return;
    float x = evec[e * 3], y = evec[e * 3 + 1], z = evec[e * 3 + 2];
    float r2 = x * x + y * y + z * z;
    if (r2 >= RMAXF * RMAXF) return;
    float r = sqrtf(r2 + 1e-12f);
    float ir = 1.0f / r;
    const float SQ3 = 1.7320508075688772f;
    int s = senders[e];
    int pos = atomicAdd(&g_zb[recv[e]], 1);
    uint4 rec;
    rec.x = __float_as_uint(r * ((float)(TBINS - 1) / RMAXF));
    __half2 h01 = __floats2half2_rn(SQ3 * x * ir, SQ3 * y * ir);
    rec.y = *reinterpret_cast<unsigned int*>(&h01);
    __half h2 = __float2half_rn(SQ3 * z * ir);
    rec.z = ((unsigned int)species[s] << 16) | (unsigned int)__half_as_ushort(h2);
    rec.w = (unsigned int)s;
    g_erec[pos] = rec;
}

// ---------------- radial-MLP LUT (fp16 rows, both layers) ----------------
__global__ void k_build_table(const float* __restrict__ mlp_w0,
                              const float* __restrict__ mlp_w1,
                              const float* __restrict__ mlp_w2) {
    __shared__ float a1[HC];
    __shared__ float a2[HC];
    __shared__ float eemb[NBC];
    __shared__ float sacc[128];
    int bin = blockIdx.x;
    int l = blockIdx.y;
    int tid = threadIdx.x;
    const float* w0 = mlp_w0 + l * NBC * HC;
    const float* w1 = mlp_w1 + l * HC * HC;
    const float* w2 = mlp_w2 + l * HC * NWC;
    if (tid < NBC) {
        float r = (float)bin * (RMAXF / (float)(TBINS - 1));
        float rs = fmaxf(r, 1e-6f);
        float ir = 1.0f / rs;
        float xr = rs * (1.0f / RMAXF);
        float x3 = xr * xr * xr, x6 = x3 * x3, x7 = x6 * xr, x8 = x7 * xr;
        float env = 1.0f - 28.0f * x6 + 48.0f * x7 - 21.0f * x8;
        const float PI_ = 3.14159265358979323846f;
        eemb[tid] = 0.6324555320336759f * ir * env * sinf(PI_ * xr * (float)(tid + 1));
    }
    __syncthreads();
    if (tid < HC) {
        float acc = 0.f;
#pragma unroll
        for (int k = 0; k < NBC; k++) acc += eemb[k] * w0[k * HC + tid];
        a1[tid] = silu(acc * 0.35355339059327373f);
    }
    __syncthreads();
    if (tid < HC) {
        float acc = 0.f;
#pragma unroll 8
        for (int k = 0; k < HC; k++) acc += a1[k] * w1[k * HC + tid];
        a2[tid] = silu(acc * 0.125f);
    }
    __syncthreads();
    {
        float acc = 0.f;
#pragma unroll 8
        for (int k = 0; k < HC; k++) acc += a2[k] * w2[k * NWC + tid];
        sacc[tid] = acc;
    }
    __syncthreads();
    if (tid < 32) {
        if (l == 0)
            g_tab0h[bin * 32 + tid] = __floats2half2_rn(sacc[tid], sacc[64 + tid]);
        else
            g_tab1h[bin * 32 + tid] = __floats2half2_rn(sacc[tid], sacc[32 + tid]);
    }
}

// ---------------- layer0 species-pure node prep + readout wcomb ----------------
__global__ void k_spec0(const float* __restrict__ embed_w,
                        const float* __restrict__ w_lin1_s,
                        const float* __restrict__ w_res_s,
                        const float* __restrict__ w_out1,
                        const float* __restrict__ w_out2) {
    int w = threadIdx.x >> 5, lane = threadIdx.x & 31;
    if (w < SC) {
        float a_hs = 0.f, a_rs0 = 0.f, a_rs1 = 0.f;
#pragma unroll 4
        for (int u = 0; u < 32; u++) {
            float x = embed_w[w * 32 + u] * 0.4472135954999579f;
            a_hs += x * w_lin1_s[u * 32 + lane];
            const float* rs = w_res_s + (size_t)(u * SC + w) * 64;
            a_rs0 += x * rs[lane];
            a_rs1 += x * rs[32 + lane];
        }
        g_s0hsl[w * 32 + lane] = a_hs * 0.17677669529663687f;
        g_s0res[w * 64 + lane] = a_rs0 * 0.07905694150420949f;
        g_s0res[w * 64 + 32 + lane] = a_rs1 * 0.07905694150420949f;
    } else if (w == SC) {
        float acc = 0.f;
#pragma unroll
        for (int k = 0; k < 16; k++) acc += w_out1[lane * 16 + k] * w_out2[k];
        g_wcomb[lane] = acc;
    }
}

// ---------------- fused layer0: gather + lin2 + residual + gate ----------------
__global__ void __launch_bounds__(128) k_gfused0(const int* __restrict__ species,
                                                 const float* __restrict__ w_lin2_s,
                                                 const float* __restrict__ w_lin2_v) {
    int n = (blockIdx.x * blockDim.x + threadIdx.x) >> 5;
    int lane = threadIdx.x & 31;
    if (n >= NN) return;
    float s0r0 = g_s0hsl[lane];
    float s0r1 = g_s0hsl[32 + lane];
    float s0r2 = g_s0hsl[64 + lane];
    float s0r3 = g_s0hsl[96 + lane];
    float s0r4 = g_s0hsl[128 + lane];
    int e = g_off[n], end = g_off[n + 1];
    float a0 = 0.f, c3x = 0.f, c3y = 0.f, c3z = 0.f;
    for (; e + 1 < end; e += 2) {
        uint4 rA = __ldg(&g_erec[e]);
        uint4 rB = __ldg(&g_erec[e + 1]);
        float pA = __uint_as_float(rA.x), pB = __uint_as_float(rB.x);
        int iA = (int)pA, iB = (int)pB;
        float fA = pA - (float)iA, fB = pB - (float)iB;
        float2 tA0 = __half22float2(g_tab0h[iA * 32 + lane]);
        float2 tA1 = __half22float2(g_tab0h[(iA + 1) * 32 + lane]);
        float2 tB0 = __half22float2(g_tab0h[iB * 32 + lane]);
        float2 tB1 = __half22float2(g_tab0h[(iB + 1) * 32 + lane]);
        float2 shA = __half22float2(*reinterpret_cast<const __half2*>(&rA.y));
        float2 shB = __half22float2(*reinterpret_cast<const __half2*>(&rB.y));
        float sh2A = __half2float(__ushort_as_half((unsigned short)(rA.z & 0xffffu)));
        float sh2B = __half2float(__ushort_as_half((unsigned short)(rB.z & 0xffffu)));
        int spA = rA.z >> 16, spB = rB.z >> 16;
        float esA = s0r0;
        esA = (spA == 1) ? s0r1 : esA;
        esA = (spA == 2) ? s0r2 : esA;
        esA = (spA == 3) ? s0r3 : esA;
        esA = (spA == 4) ? s0r4 : esA;
        float esB = s0r0;
        esB = (spB == 1) ? s0r1 : esB;
        esB = (spB == 2) ? s0r2 : esB;
        esB = (spB == 3) ? s0r3 : esB;
        esB = (spB == 4) ? s0r4 : esB;
        float w1A = fmaf(fA, tA1.x - tA0.x, tA0.x);
        float w3A = fmaf(fA, tA1.y - tA0.y, tA0.y);
        float w1B = fmaf(fB, tB1.x - tB0.x, tB0.x);
        float w3B = fmaf(fB, tB1.y - tB0.y, tB0.y);
        a0 += w1A * esA + w1B * esB;
        float wA = w3A * esA, wB = w3B * esB;
        c3x += wA * shA.x + wB * shB.x;
        c3y += wA * shA.y + wB * shB.y;
        c3z += wA * sh2A + wB * sh2B;
    }
    if (e < end) {
        uint4 rA = __ldg(&g_erec[e]);
        float pA = __uint_as_float(rA.x);
        int iA = (int)pA;
        float fA = pA - (float)iA;
        float2 tA0 = __half22float2(g_tab0h[iA * 32 + lane]);
        float2 tA1 = __half22float2(g_tab0h[(iA + 1) * 32 + lane]);
        float2 shA = __half22float2(*reinterpret_cast<const __half2*>(&rA.y));
        float sh2A = __half2float(__ushort_as_half((unsigned short)(rA.z & 0xffffu)));
        int spA = rA.z >> 16;
        float esA = s0r0;
        esA = (spA == 1) ? s0r1 : esA;
        esA = (spA == 2) ? s0r2 : esA;
        esA = (spA == 3) ? s0r3 : esA;
        esA = (spA == 4) ? s0r4 : esA;
        float w1A = fmaf(fA, tA1.x - tA0.x, tA0.x);
        float w3A = fmaf(fA, tA1.y - tA0.y, tA0.y);
        a0 += w1A * esA;
        float wA = w3A * esA;
        c3x += wA * shA.x; c3y += wA * shA.y; c3z += wA * sh2A;
    }
    // ---- fused lin2 + residual + gate via shuffle contraction ----
    float s0 = 0.f, s1 = 0.f, v0 = 0.f, v1 = 0.f, v2 = 0.f;
#pragma unroll 4
    for (int j = 0; j < 32; j++) {
        float xj = __shfl_sync(0xffffffffu, a0, j);
        float c0 = __shfl_sync(0xffffffffu, c3x, j);
        float c1 = __shfl_sync(0xffffffffu, c3y, j);
        float c2 = __shfl_sync(0xffffffffu, c3z, j);
        float wa = w_lin2_s[j * 64 + lane];
        float wb = w_lin2_s[j * 64 + 32 + lane];
        float wc = w_lin2_v[j * 32 + lane];
        s0 += xj * wa;
        s1 += xj * wb;
        v0 += c0 * wc; v1 += c1 * wc; v2 += c2 * wc;
    }
    const float SC_ = 0.0078125f;
    int sp = species[n];
    float hs = silu(s0 * SC_ + g_s0res[sp * 64 + lane]);
    float gate = silu(s1 * SC_ + g_s0res[sp * 64 + 32 + lane]);
    g_hs[n * 32 + lane] = hs;
    g_hv[(n * 3 + 0) * 32 + lane] = v0 * SC_ * gate;
    g_hv[(n * 3 + 1) * 32 + lane] = v1 * SC_ * gate;
    g_hv[(n * 3 + 2) * 32 + lane] = v2 * SC_ * gate;
}

// ---------------- layer1 prep ----------------
__global__ void __launch_bounds__(256) k_prep1(const int* __restrict__ species,
                                               const float* __restrict__ w_res_s,
                                               const float* __restrict__ w_lin1_s,
                                               const float* __restrict__ w_lin1_v) {
    int w = (blockIdx.x * blockDim.x + threadIdx.x) >> 5;
    int lane = threadIdx.x & 31;
    int base = w * 8;
    if (base >= NN) return;
    int nid[8], sp[8];
#pragma unroll
    for (int g = 0; g < 8; g++) { nid[g] = g_nsort[base + g]; sp[g] = species[nid[g]]; }
    bool uni = true;
#pragma unroll
    for (int g = 1; g < 8; g++) uni = uni && (sp[g] == sp[0]);
    const float* Wl1s = w_lin1_s + 1024;
    const float* Wl1v = w_lin1_v + 1024;
    float a_hs[8] = {0}, a_rs0[8] = {0}, a_hv[8][3] = {{0}};
#pragma unroll 2
    for (int uc = 0; uc < 8; uc++) {
        int u0 = uc * 4;
        float ws[4], wv[4], wr0[4];
#pragma unroll
        for (int d = 0; d < 4; d++) {
            ws[d] = Wl1s[(u0 + d) * 32 + lane];
            wv[d] = Wl1v[(u0 + d) * 32 + lane];
        }
        if (uni) {
#pragma unroll
            for (int d = 0; d < 4; d++)
                wr0[d] = w_res_s[(size_t)(((32 + u0 + d) * SC) + sp[0]) * 64 + lane];
        }
#pragma unroll
        for (int g = 0; g < 8; g++) {
            float r0[4];
            if (uni) {
#pragma unroll
                for (int d = 0; d < 4; d++) r0[d] = wr0[d];
            } else {
#pragma unroll
                for (int d = 0; d < 4; d++)
                    r0[d] = w_res_s[(size_t)(((32 + u0 + d) * SC) + sp[g]) * 64 + lane];
            }
            float4 xs = *reinterpret_cast<const float4*>(&g_hs[nid[g] * 32 + u0]);
            float xa[4] = {xs.x, xs.y, xs.z, xs.w};
#pragma unroll
            for (int d = 0; d < 4; d++) {
                a_hs[g] += xa[d] * ws[d];
                a_rs0[g] += xa[d] * r0[d];
            }
#pragma unroll
            for (int i = 0; i < 3; i++) {
                float4 xv = *reinterpret_cast<const float4*>(&g_hv[(nid[g] * 3 + i) * 32 + u0]);
                a_hv[g][i] += xv.x * wv[0] + xv.y * wv[1] + xv.z * wv[2] + xv.w * wv[3];
            }
        }
    }
    const float IS32 = 0.17677669529663687f;
    const float IS160 = 0.07905694150420949f;
#pragma unroll
    for (int g = 0; g < 8; g++) {
        int n = nid[g];
        g_feath[n * 64 + lane * 2] = __floats2half2_rn(a_hs[g] * IS32, a_hv[g][0] * IS32);
        g_feath[n * 64 + lane * 2 + 1] = __floats2half2_rn(a_hv[g][1] * IS32, a_hv[g][2] * IS32);
        g_res1s[n * 32 + lane] = a_rs0[g] * IS160;
    }
}

// ---------------- fused layer1: gather + lin2 + residual + readout ----------------
__global__ void __launch_bounds__(128) k_gfused1(const float* __restrict__ w_lin2_s,
                                                 float* __restrict__ out) {
    int n = (blockIdx.x * blockDim.x + threadIdx.x) >> 5;
    int lane = threadIdx.x & 31;
    if (n >= NN) return;
    int e = g_off[n], end = g_off[n + 1];
    float a0 = 0.f, a1 = 0.f;
    for (; e + 1 < end; e += 2) {
        uint4 rA = __ldg(&g_erec[e]);
        uint4 rB = __ldg(&g_erec[e + 1]);
        float pA = __uint_as_float(rA.x), pB = __uint_as_float(rB.x);
        int iA = (int)pA, iB = (int)pB;
        float fA = pA - (float)iA, fB = pB - (float)iB;
        float2 tA0 = __half22float2(g_tab1h[iA * 32 + lane]);
        float2 tA1 = __half22float2(g_tab1h[(iA + 1) * 32 + lane]);
        float2 tB0 = __half22float2(g_tab1h[iB * 32 + lane]);
        float2 tB1 = __half22float2(g_tab1h[(iB + 1) * 32 + lane]);
        uint2 fwA = __ldg(reinterpret_cast<const uint2*>(&g_feath[(int)rA.w * 64 + lane * 2]));
        uint2 fwB = __ldg(reinterpret_cast<const uint2*>(&g_feath[(int)rB.w * 64 + lane * 2]));
        float2 fA0 = __half22float2(*reinterpret_cast<const __half2*>(&fwA.x));
        float2 fA1 = __half22float2(*reinterpret_cast<const __half2*>(&fwA.y));
        float2 fB0 = __half22float2(*reinterpret_cast<const __half2*>(&fwB.x));
        float2 fB1 = __half22float2(*reinterpret_cast<const __half2*>(&fwB.y));
        float2 shA = __half22float2(*reinterpret_cast<const __half2*>(&rA.y));
        float2 shB = __half22float2(*reinterpret_cast<const __half2*>(&rB.y));
        float sh2A = __half2float(__ushort_as_half((unsigned short)(rA.z & 0xffffu)));
        float sh2B = __half2float(__ushort_as_half((unsigned short)(rB.z & 0xffffu)));
        float w1A = fmaf(fA, tA1.x - tA0.x, tA0.x);
        float w2A = fmaf(fA, tA1.y - tA0.y, tA0.y);
        float w1B = fmaf(fB, tB1.x - tB0.x, tB0.x);
        float w2B = fmaf(fB, tB1.y - tB0.y, tB0.y);
        a0 += w1A * fA0.x + w1B * fB0.x;
        float dA = fA0.y * shA.x + fA1.x * shA.y + fA1.y * sh2A;
        float dB = fB0.y * shB.x + fB1.x * shB.y + fB1.y * sh2B;
        a1 += w2A * dA + w2B * dB;
    }
    if (e < end) {
        uint4 rA = __ldg(&g_erec[e]);
        float pA = __uint_as_float(rA.x);
        int iA = (int)pA;
        float fA = pA - (float)iA;
        float2 tA0 = __half22float2(g_tab1h[iA * 32 + lane]);
        float2 tA1 = __half22float2(g_tab1h[(iA + 1) * 32 + lane]);
        uint2 fwA = __ldg(reinterpret_cast<const uint2*>(&g_feath[(int)rA.w * 64 + lane * 2]));
        float2 fA0 = __half22float2(*reinterpret_cast<const __half2*>(&fwA.x));
        float2 fA1 = __half22float2(*reinterpret_cast<const __half2*>(&fwA.y));
        float2 shA = __half22float2(*reinterpret_cast<const __half2*>(&rA.y));
        float sh2A = __half2float(__ushort_as_half((unsigned short)(rA.z & 0xffffu)));
        float w1A = fmaf(fA, tA1.x - tA0.x, tA0.x);
        float w2A = fmaf(fA, tA1.y - tA0.y, tA0.y);
        a0 += w1A * fA0.x;
        a1 += w2A * (fA0.y * shA.x + fA1.x * shA.y + fA1.y * sh2A);
    }
    // ---- fused lin2 (scalar half only) + residual + readout ----
    float a1s = a1 * 0.5773502691896258f;
    const float* W2s = w_lin2_s + 4096;  // l=1
    float s0 = 0.f;
#pragma unroll 4
    for (int j = 0; j < 32; j++) {
        float xj = __shfl_sync(0xffffffffu, a0, j);
        s0 += xj * W2s[j * 64 + lane];
    }
#pragma unroll 4
    for (int j = 32; j < 64; j++) {
        float xj = __shfl_sync(0xffffffffu, a1s, j - 32);
        s0 += xj * W2s[j * 64 + lane];
    }
    const float SC_ = 0.0078125f;
    float hs = silu(s0 * SC_ + g_res1s[n * 32 + lane]);
    float z = hs * g_wcomb[lane];
    z += __shfl_xor_sync(0xffffffffu, z, 16);
    z += __shfl_xor_sync(0xffffffffu, z, 8);
    z += __shfl_xor_sync(0xffffffffu, z, 4);
    z += __shfl_xor_sync(0xffffffffu, z, 2);
    z += __shfl_xor_sync(0xffffffffu, z, 1);
    if (lane == 0) out[n] = z * (0.17677669529663687f * 0.25f);
}

// ---------------- launch ----------------
extern "C" void kernel_launch(void* const* d_in, const int* in_sizes, int n_in,
                              void* d_out, int out_size) {
    const float* edge_vectors = (const float*)d_in[0];
    const int* species        = (const int*)d_in[1];
    const int* senders        = (const int*)d_in[2];
    const int* receivers      = (const int*)d_in[3];
    const float* embed_w      = (const float*)d_in[4];
    const float* w_res_s      = (const float*)d_in[5];
    const float* w_lin1_s     = (const float*)d_in[7];
    const float* w_lin1_v     = (const float*)d_in[8];
    const float* mlp_w0       = (const float*)d_in[9];
    const float* mlp_w1       = (const float*)d_in[10];
    const float* mlp_w2       = (const float*)d_in[11];
    const float* w_lin2_s     = (const float*)d_in[12];
    const float* w_lin2_v     = (const float*)d_in[13];
    const float* w_out1       = (const float*)d_in[14];
    const float* w_out2       = (const float*)d_in[15];
    float* out = (float*)d_out;

    static cudaStream_t s2 = nullptr;
    static cudaEvent_t evA = nullptr, evB = nullptr;
    if (!s2) {
        cudaStreamCreateWithFlags(&s2, cudaStreamNonBlocking);
        cudaEventCreateWithFlags(&evA, cudaEventDisableTiming);
        cudaEventCreateWithFlags(&evB, cudaEventDisableTiming);
    }

    void* zb_ptr = nullptr;
    cudaGetSymbolAddress(&zb_ptr, g_zb);

    const int EB256 = (EE + 255) / 256;
    const int GPB = (NN + 3) / 4;          // fused gathers: 128-thr blocks, warp per node
    const int WPB8 = (NN / 8 + 7) / 8;

    // fork: side stream builds LUT + species-pure prep, overlapping the CSR chain
    cudaEventRecord(evA, 0);
    cudaStreamWaitEvent(s2, evA, 0);
    k_build_table<<<dim3(TBINS, 2), 128, 0, s2>>>(mlp_w0, mlp_w1, mlp_w2);
    k_spec0<<<1, 192, 0, s2>>>(embed_w, w_lin1_s, w_res_s, w_out1, w_out2);
    cudaEventRecord(evB, s2);

    // main chain: CSR build
    cudaMemsetAsync(zb_ptr, 0, (NN + 16 + NODE_BLOCKS) * sizeof(int));
    k_hist<<<EB256, 256>>>(edge_vectors, receivers, species);
    k_scan<<<NODE_BLOCKS, 256>>>();
    k_scatter<<<EB256, 256>>>(edge_vectors, senders, receivers, species);

    // join, then fused layers
    cudaStreamWaitEvent(0, evB, 0);
    k_gfused0<<<GPB, 128>>>(species, w_lin2_s, w_lin2_v);
    k_prep1<<<WPB8, 256>>>(species, w_res_s, w_lin1_s, w_lin1_v);
    k_gfused1<<<GPB, 128>>>(w_lin2_s, out);
}

// round 10
// speedup vs baseline: 7.5268x; 1.0818x over previous
#include <cuda_runtime.h>
#include <cuda_fp16.h>

#define NN 50000
#define EE 800000
#define SC 5
#define NBC 8
#define HC 64
#define NWC 128
#define TBINS 1024
#define RMAXF 5.0f

#define NODE_BLOCKS 196         // 196*256 >= NN

// ---------------- device scratch ----------------
// g_zb layout: [0,NN) degree->cursor; [NN,NN+5) species counts; [NN+16, NN+16+NODE_BLOCKS) lookback states
__device__ int g_zb[NN + 16 + NODE_BLOCKS];
__device__ int g_off[NN + 1];
__device__ int g_scur[SC];
__device__ int g_nsort[NN];
__device__ uint4 g_erec[EE];             // packed CSR edge record: p | sh01 | (spec<<16|sh2) | sender
__device__ float g_hs[NN * 32];
__device__ float g_hv[NN * 96];
__device__ __half2 g_feath[NN * 64];     // layer1 feats: (es,ev0),(ev1,ev2)
__device__ float g_res1s[NN * 32];
__device__ __half2 g_tab0h[TBINS * 32];  // layer0 LUT (w1, w3)  — 128 KB, L1-resident
__device__ __half2 g_tab1h[TBINS * 32];  // layer1 LUT (w1, w2)
__device__ float g_s0hsl[SC * 32];
__device__ float g_s0res[SC * 64];
__device__ float g_wcomb[32];            // readout combined weights

__device__ __forceinline__ float silu(float x) { return x / (1.0f + __expf(-x)); }

// ---------------- hist: degree + species counts ----------------
__global__ void k_hist(const float* __restrict__ evec, const int* __restrict__ recv,
                       const int* __restrict__ species) {
    int e = blockIdx.x * blockDim.x + threadIdx.x;
    if (e < NN) atomicAdd(&g_zb[NN + species[e]], 1);
    if (e >= EE) return;
    float x = evec[e * 3], y = evec[e * 3 + 1], z = evec[e * 3 + 2];
    if (x * x + y * y + z * z < RMAXF * RMAXF) atomicAdd(&g_zb[recv[e]], 1);
}

// ---------------- single-pass scan, warp-parallel decoupled lookback ----------------
#define FLAGP 0x40000000u
#define FLAGX 0x80000000u
#define VALM  0x3FFFFFFFu

__global__ void __launch_bounds__(256) k_scan() {
    __shared__ int ws[8];
    __shared__ int s_tot, s_off;
    int b = blockIdx.x, t = threadIdx.x;
    int lane = t & 31, wid = t >> 5;
    int idx = b * 256 + t;
    int v = (idx < NN) ? g_zb[idx] : 0;
    int x = v;
#pragma unroll
    for (int d = 1; d < 32; d <<= 1) {
        int y = __shfl_up_sync(0xffffffffu, x, d);
        if (lane >= d) x += y;
    }
    if (lane == 31) ws[wid] = x;
    __syncthreads();
    if (wid == 0 && lane < 8) {
        int s = ws[lane];
#pragma unroll
        for (int d = 1; d < 8; d <<= 1) {
            int y = __shfl_up_sync(0xffu, s, d);
            if (lane >= d) s += y;
        }
        ws[lane] = s;
    }
    __syncthreads();
    int incl = x + (wid > 0 ? ws[wid - 1] : 0);
    if (t == 255) s_tot = incl;
    __syncthreads();
    unsigned int* look = reinterpret_cast<unsigned int*>(&g_zb[NN + 16]);
    if (wid == 0) {
        if (b == 0) {
            if (lane == 0) {
                int a2 = 0;   // species prefix (hist done)
                for (int s = 0; s < SC; s++) { g_scur[s] = a2; a2 += g_zb[NN + s]; }
                s_off = 0;
                atomicExch(&look[0], (unsigned)s_tot | FLAGX);
            }
        } else {
            if (lane == 0) atomicExch(&look[b], (unsigned)s_tot | FLAGP);
            int run = 0, j = b;
            while (true) {
                int pidx = j - 1 - lane;
                unsigned st = FLAGX;   // OOB lanes contribute value 0 with X-flag
                if (pidx >= 0) {
                    while ((((st = atomicAdd(&look[pidx], 0u))) & (FLAGP | FLAGX)) == 0u)
                        __nanosleep(32);
                }
                unsigned xmask = __ballot_sync(0xffffffffu, (st & FLAGX) != 0u);
                int val = (int)(st & VALM);
                if (xmask) {
                    int firstx = __ffs(xmask) - 1;   // nearest predecessor with inclusive sum
                    int contrib = (lane <= firstx) ? val : 0;
#pragma unroll
                    for (int d = 16; d > 0; d >>= 1)
                        contrib += __shfl_xor_sync(0xffffffffu, contrib, d);
                    run += contrib;
                    break;
                } else {
                    int contrib = val;
#pragma unroll
                    for (int d = 16; d > 0; d >>= 1)
                        contrib += __shfl_xor_sync(0xffffffffu, contrib, d);
                    run += contrib;
                    j -= 32;
                }
            }
            if (lane == 0) {
                s_off = run;
                atomicExch(&look[b], (unsigned)(run + s_tot) | FLAGX);
            }
        }
        if (b == NODE_BLOCKS - 1 && lane == 0) g_off[NN] = s_off + s_tot;
    }
    __syncthreads();
    if (idx < NN) {
        int o = incl - v + s_off;
        g_off[idx] = o;
        g_zb[idx] = o;   // cursor for scatter
    }
}

// ---------------- scatter: packed 16B record + species-sorted node list ----------------
__global__ void k_scatter(const float* __restrict__ evec, const int* __restrict__ senders,
                          const int* __restrict__ recv, const int* __restrict__ species) {
    int e = blockIdx.x * blockDim.x + threadIdx.x;
    if (e < NN) {
        int pos = atomicAdd(&g_scur[species[e]], 1);
        g_nsort[pos] = e;
    }
    if (e >= EE) return;
    float x = evec[e * 3], y = evec[e * 3 + 1], z = evec[e * 3 + 2];
    float r2 = x * x + y * y + z * z;
    if (r2 >= RMAXF * RMAXF) return;
    float r = sqrtf(r2 + 1e-12f);
    float ir = 1.0f / r;
    const float SQ3 = 1.7320508075688772f;
    int s = senders[e];
    int pos = atomicAdd(&g_zb[recv[e]], 1);
    uint4 rec;
    rec.x = __float_as_uint(r * ((float)(TBINS - 1) / RMAXF));
    __half2 h01 = __floats2half2_rn(SQ3 * x * ir, SQ3 * y * ir);
    rec.y = *reinterpret_cast<unsigned int*>(&h01);
    __half h2 = __float2half_rn(SQ3 * z * ir);
    rec.z = ((unsigned int)species[s] << 16) | (unsigned int)__half_as_ushort(h2);
    rec.w = (unsigned int)s;
    g_erec[pos] = rec;
}

// ---------------- radial-MLP LUT (fp16 rows, both layers) ----------------
__global__ void k_build_table(const float* __restrict__ mlp_w0,
                              const float* __restrict__ mlp_w1,
                              const float* __restrict__ mlp_w2) {
    __shared__ float a1[HC];
    __shared__ float a2[HC];
    __shared__ float eemb[NBC];
    __shared__ float sacc[128];
    int bin = blockIdx.x;
    int l = blockIdx.y;
    int tid = threadIdx.x;
    const float* w0 = mlp_w0 + l * NBC * HC;
    const float* w1 = mlp_w1 + l * HC * HC;
    const float* w2 = mlp_w2 + l * HC * NWC;
    if (tid < NBC) {
        float r = (float)bin * (RMAXF / (float)(TBINS - 1));
        float rs = fmaxf(r, 1e-6f);
        float ir = 1.0f / rs;
        float xr = rs * (1.0f / RMAXF);
        float x3 = xr * xr * xr, x6 = x3 * x3, x7 = x6 * xr, x8 = x7 * xr;
        float env = 1.0f - 28.0f * x6 + 48.0f * x7 - 21.0f * x8;
        const float PI_ = 3.14159265358979323846f;
        eemb[tid] = 0.6324555320336759f * ir * env * sinf(PI_ * xr * (float)(tid + 1));
    }
    __syncthreads();
    if (tid < HC) {
        float acc = 0.f;
#pragma unroll
        for (int k = 0; k < NBC; k++) acc += eemb[k] * w0[k * HC + tid];
        a1[tid] = silu(acc * 0.35355339059327373f);
    }
    __syncthreads();
    if (tid < HC) {
        float acc = 0.f;
#pragma unroll 8
        for (int k = 0; k < HC; k++) acc += a1[k] * w1[k * HC + tid];
        a2[tid] = silu(acc * 0.125f);
    }
    __syncthreads();
    {
        float acc = 0.f;
#pragma unroll 8
        for (int k = 0; k < HC; k++) acc += a2[k] * w2[k * NWC + tid];
        sacc[tid] = acc;
    }
    __syncthreads();
    if (tid < 32) {
        if (l == 0)
            g_tab0h[bin * 32 + tid] = __floats2half2_rn(sacc[tid], sacc[64 + tid]);
        else
            g_tab1h[bin * 32 + tid] = __floats2half2_rn(sacc[tid], sacc[32 + tid]);
    }
}

// ---------------- layer0 species-pure node prep + readout wcomb ----------------
__global__ void k_spec0(const float* __restrict__ embed_w,
                        const float* __restrict__ w_lin1_s,
                        const float* __restrict__ w_res_s,
                        const float* __restrict__ w_out1,
                        const float* __restrict__ w_out2) {
    int w = threadIdx.x >> 5, lane = threadIdx.x & 31;
    if (w < SC) {
        float a_hs = 0.f, a_rs0 = 0.f, a_rs1 = 0.f;
#pragma unroll 4
        for (int u = 0; u < 32; u++) {
            float x = embed_w[w * 32 + u] * 0.4472135954999579f;
            a_hs += x * w_lin1_s[u * 32 + lane];
            const float* rs = w_res_s + (size_t)(u * SC + w) * 64;
            a_rs0 += x * rs[lane];
            a_rs1 += x * rs[32 + lane];
        }
        g_s0hsl[w * 32 + lane] = a_hs * 0.17677669529663687f;
        g_s0res[w * 64 + lane] = a_rs0 * 0.07905694150420949f;
        g_s0res[w * 64 + 32 + lane] = a_rs1 * 0.07905694150420949f;
    } else if (w == SC) {
        float acc = 0.f;
#pragma unroll
        for (int k = 0; k < 16; k++) acc += w_out1[lane * 16 + k] * w_out2[k];
        g_wcomb[lane] = acc;
    }
}

// ---------------- fused layer0: gather(4x unroll) + lin2 + residual + gate ----------------
__global__ void __launch_bounds__(128) k_gfused0(const int* __restrict__ species,
                                                 const float* __restrict__ w_lin2_s,
                                                 const float* __restrict__ w_lin2_v) {
    int n = (blockIdx.x * blockDim.x + threadIdx.x) >> 5;
    int lane = threadIdx.x & 31;
    if (n >= NN) return;
    float sr[SC];
#pragma unroll
    for (int s = 0; s < SC; s++) sr[s] = g_s0hsl[s * 32 + lane];
    int e = g_off[n], end = g_off[n + 1];
    float a0 = 0.f, c3x = 0.f, c3y = 0.f, c3z = 0.f;
    for (; e + 3 < end; e += 4) {
        uint4 r[4];
#pragma unroll
        for (int k = 0; k < 4; k++) r[k] = __ldcs(&g_erec[e + k]);
#pragma unroll
        for (int k = 0; k < 4; k++) {
            float p = __uint_as_float(r[k].x);
            int i = (int)p;
            float f = p - (float)i;
            float2 t0 = __half22float2(g_tab0h[i * 32 + lane]);
            float2 t1 = __half22float2(g_tab0h[(i + 1) * 32 + lane]);
            float2 sh = __half22float2(*reinterpret_cast<const __half2*>(&r[k].y));
            float sh2 = __half2float(__ushort_as_half((unsigned short)(r[k].z & 0xffffu)));
            int sp = r[k].z >> 16;
            float es = sr[0];
            es = (sp == 1) ? sr[1] : es;
            es = (sp == 2) ? sr[2] : es;
            es = (sp == 3) ? sr[3] : es;
            es = (sp == 4) ? sr[4] : es;
            float w1 = fmaf(f, t1.x - t0.x, t0.x);
            float w3 = fmaf(f, t1.y - t0.y, t0.y);
            a0 += w1 * es;
            float wv = w3 * es;
            c3x += wv * sh.x; c3y += wv * sh.y; c3z += wv * sh2;
        }
    }
    for (; e < end; e++) {
        uint4 rA = __ldcs(&g_erec[e]);
        float p = __uint_as_float(rA.x);
        int i = (int)p;
        float f = p - (float)i;
        float2 t0 = __half22float2(g_tab0h[i * 32 + lane]);
        float2 t1 = __half22float2(g_tab0h[(i + 1) * 32 + lane]);
        float2 sh = __half22float2(*reinterpret_cast<const __half2*>(&rA.y));
        float sh2 = __half2float(__ushort_as_half((unsigned short)(rA.z & 0xffffu)));
        int sp = rA.z >> 16;
        float es = sr[0];
        es = (sp == 1) ? sr[1] : es;
        es = (sp == 2) ? sr[2] : es;
        es = (sp == 3) ? sr[3] : es;
        es = (sp == 4) ? sr[4] : es;
        float w1 = fmaf(f, t1.x - t0.x, t0.x);
        float w3 = fmaf(f, t1.y - t0.y, t0.y);
        a0 += w1 * es;
        float wv = w3 * es;
        c3x += wv * sh.x; c3y += wv * sh.y; c3z += wv * sh2;
    }
    // ---- fused lin2 + residual + gate via shuffle contraction ----
    float s0 = 0.f, s1 = 0.f, v0 = 0.f, v1 = 0.f, v2 = 0.f;
#pragma unroll 4
    for (int j = 0; j < 32; j++) {
        float xj = __shfl_sync(0xffffffffu, a0, j);
        float c0 = __shfl_sync(0xffffffffu, c3x, j);
        float c1 = __shfl_sync(0xffffffffu, c3y, j);
        float c2 = __shfl_sync(0xffffffffu, c3z, j);
        float wa = w_lin2_s[j * 64 + lane];
        float wb = w_lin2_s[j * 64 + 32 + lane];
        float wc = w_lin2_v[j * 32 + lane];
        s0 += xj * wa;
        s1 += xj * wb;
        v0 += c0 * wc; v1 += c1 * wc; v2 += c2 * wc;
    }
    const float SC_ = 0.0078125f;
    int sp = species[n];
    float hs = silu(s0 * SC_ + g_s0res[sp * 64 + lane]);
    float gate = silu(s1 * SC_ + g_s0res[sp * 64 + 32 + lane]);
    g_hs[n * 32 + lane] = hs;
    g_hv[(n * 3 + 0) * 32 + lane] = v0 * SC_ * gate;
    g_hv[(n * 3 + 1) * 32 + lane] = v1 * SC_ * gate;
    g_hv[(n * 3 + 2) * 32 + lane] = v2 * SC_ * gate;
}

// ---------------- layer1 prep ----------------
__global__ void __launch_bounds__(256) k_prep1(const int* __restrict__ species,
                                               const float* __restrict__ w_res_s,
                                               const float* __restrict__ w_lin1_s,
                                               const float* __restrict__ w_lin1_v) {
    int w = (blockIdx.x * blockDim.x + threadIdx.x) >> 5;
    int lane = threadIdx.x & 31;
    int base = w * 8;
    if (base >= NN) return;
    int nid[8], sp[8];
#pragma unroll
    for (int g = 0; g < 8; g++) { nid[g] = g_nsort[base + g]; sp[g] = species[nid[g]]; }
    bool uni = true;
#pragma unroll
    for (int g = 1; g < 8; g++) uni = uni && (sp[g] == sp[0]);
    const float* Wl1s = w_lin1_s + 1024;
    const float* Wl1v = w_lin1_v + 1024;
    float a_hs[8] = {0}, a_rs0[8] = {0}, a_hv[8][3] = {{0}};
#pragma unroll 2
    for (int uc = 0; uc < 8; uc++) {
        int u0 = uc * 4;
        float ws[4], wv[4], wr0[4];
#pragma unroll
        for (int d = 0; d < 4; d++) {
            ws[d] = Wl1s[(u0 + d) * 32 + lane];
            wv[d] = Wl1v[(u0 + d) * 32 + lane];
        }
        if (uni) {
#pragma unroll
            for (int d = 0; d < 4; d++)
                wr0[d] = w_res_s[(size_t)(((32 + u0 + d) * SC) + sp[0]) * 64 + lane];
        }
#pragma unroll
        for (int g = 0; g < 8; g++) {
            float r0[4];
            if (uni) {
#pragma unroll
                for (int d = 0; d < 4; d++) r0[d] = wr0[d];
            } else {
#pragma unroll
                for (int d = 0; d < 4; d++)
                    r0[d] = w_res_s[(size_t)(((32 + u0 + d) * SC) + sp[g]) * 64 + lane];
            }
            float4 xs = *reinterpret_cast<const float4*>(&g_hs[nid[g] * 32 + u0]);
            float xa[4] = {xs.x, xs.y, xs.z, xs.w};
#pragma unroll
            for (int d = 0; d < 4; d++) {
                a_hs[g] += xa[d] * ws[d];
                a_rs0[g] += xa[d] * r0[d];
            }
#pragma unroll
            for (int i = 0; i < 3; i++) {
                float4 xv = *reinterpret_cast<const float4*>(&g_hv[(nid[g] * 3 + i) * 32 + u0]);
                a_hv[g][i] += xv.x * wv[0] + xv.y * wv[1] + xv.z * wv[2] + xv.w * wv[3];
            }
        }
    }
    const float IS32 = 0.17677669529663687f;
    const float IS160 = 0.07905694150420949f;
#pragma unroll
    for (int g = 0; g < 8; g++) {
        int n = nid[g];
        g_feath[n * 64 + lane * 2] = __floats2half2_rn(a_hs[g] * IS32, a_hv[g][0] * IS32);
        g_feath[n * 64 + lane * 2 + 1] = __floats2half2_rn(a_hv[g][1] * IS32, a_hv[g][2] * IS32);
        g_res1s[n * 32 + lane] = a_rs0[g] * IS160;
    }
}

// ---------------- fused layer1: gather(4x unroll) + lin2 + residual + readout ----------------
__global__ void __launch_bounds__(128) k_gfused1(const float* __restrict__ w_lin2_s,
                                                 float* __restrict__ out) {
    int n = (blockIdx.x * blockDim.x + threadIdx.x) >> 5;
    int lane = threadIdx.x & 31;
    if (n >= NN) return;
    int e = g_off[n], end = g_off[n + 1];
    float a0 = 0.f, a1 = 0.f;
    for (; e + 3 < end; e += 4) {
        uint4 r[4];
        uint2 fw[4];
#pragma unroll
        for (int k = 0; k < 4; k++) r[k] = __ldcs(&g_erec[e + k]);
#pragma unroll
        for (int k = 0; k < 4; k++)
            fw[k] = __ldcs(reinterpret_cast<const uint2*>(&g_feath[(int)r[k].w * 64 + lane * 2]));
#pragma unroll
        for (int k = 0; k < 4; k++) {
            float p = __uint_as_float(r[k].x);
            int i = (int)p;
            float f = p - (float)i;
            float2 t0 = __half22float2(g_tab1h[i * 32 + lane]);
            float2 t1 = __half22float2(g_tab1h[(i + 1) * 32 + lane]);
            float2 f0 = __half22float2(*reinterpret_cast<const __half2*>(&fw[k].x));
            float2 f1 = __half22float2(*reinterpret_cast<const __half2*>(&fw[k].y));
            float2 sh = __half22float2(*reinterpret_cast<const __half2*>(&r[k].y));
            float sh2 = __half2float(__ushort_as_half((unsigned short)(r[k].z & 0xffffu)));
            float w1 = fmaf(f, t1.x - t0.x, t0.x);
            float w2 = fmaf(f, t1.y - t0.y, t0.y);
            a0 += w1 * f0.x;
            a1 += w2 * (f0.y * sh.x + f1.x * sh.y + f1.y * sh2);
        }
    }
    for (; e < end; e++) {
        uint4 rA = __ldcs(&g_erec[e]);
        float p = __uint_as_float(rA.x);
        int i = (int)p;
        float f = p - (float)i;
        float2 t0 = __half22float2(g_tab1h[i * 32 + lane]);
        float2 t1 = __half22float2(g_tab1h[(i + 1) * 32 + lane]);
        uint2 fwA = __ldcs(reinterpret_cast<const uint2*>(&g_feath[(int)rA.w * 64 + lane * 2]));
        float2 f0 = __half22float2(*reinterpret_cast<const __half2*>(&fwA.x));
        float2 f1 = __half22float2(*reinterpret_cast<const __half2*>(&fwA.y));
        float2 sh = __half22float2(*reinterpret_cast<const __half2*>(&rA.y));
        float sh2 = __half2float(__ushort_as_half((unsigned short)(rA.z & 0xffffu)));
        float w1 = fmaf(f, t1.x - t0.x, t0.x);
        float w2 = fmaf(f, t1.y - t0.y, t0.y);
        a0 += w1 * f0.x;
        a1 += w2 * (f0.y * sh.x + f1.x * sh.y + f1.y * sh2);
    }
    // ---- fused lin2 (scalar half only) + residual + readout ----
    float a1s = a1 * 0.5773502691896258f;
    const float* W2s = w_lin2_s + 4096;  // l=1
    float s0 = 0.f;
#pragma unroll 4
    for (int j = 0; j < 32; j++) {
        float xj = __shfl_sync(0xffffffffu, a0, j);
        s0 += xj * W2s[j * 64 + lane];
    }
#pragma unroll 4
    for (int j = 32; j < 64; j++) {
        float xj = __shfl_sync(0xffffffffu, a1s, j - 32);
        s0 += xj * W2s[j * 64 + lane];
    }
    const float SC_ = 0.0078125f;
    float hs = silu(s0 * SC_ + g_res1s[n * 32 + lane]);
    float z = hs * g_wcomb[lane];
    z += __shfl_xor_sync(0xffffffffu, z, 16);
    z += __shfl_xor_sync(0xffffffffu, z, 8);
    z += __shfl_xor_sync(0xffffffffu, z, 4);
    z += __shfl_xor_sync(0xffffffffu, z, 2);
    z += __shfl_xor_sync(0xffffffffu, z, 1);
    if (lane == 0) out[n] = z * (0.17677669529663687f * 0.25f);
}

// ---------------- launch ----------------
extern "C" void kernel_launch(void* const* d_in, const int* in_sizes, int n_in,
                              void* d_out, int out_size) {
    const float* edge_vectors = (const float*)d_in[0];
    const int* species        = (const int*)d_in[1];
    const int* senders        = (const int*)d_in[2];
    const int* receivers      = (const int*)d_in[3];
    const float* embed_w      = (const float*)d_in[4];
    const float* w_res_s      = (const float*)d_in[5];
    const float* w_lin1_s     = (const float*)d_in[7];
    const float* w_lin1_v     = (const float*)d_in[8];
    const float* mlp_w0       = (const float*)d_in[9];
    const float* mlp_w1       = (const float*)d_in[10];
    const float* mlp_w2       = (const float*)d_in[11];
    const float* w_lin2_s     = (const float*)d_in[12];
    const float* w_lin2_v     = (const float*)d_in[13];
    const float* w_out1       = (const float*)d_in[14];
    const float* w_out2       = (const float*)d_in[15];
    float* out = (float*)d_out;

    static cudaStream_t s2 = nullptr;
    static cudaEvent_t evA = nullptr, evB = nullptr;
    if (!s2) {
        cudaStreamCreateWithFlags(&s2, cudaStreamNonBlocking);
        cudaEventCreateWithFlags(&evA, cudaEventDisableTiming);
        cudaEventCreateWithFlags(&evB, cudaEventDisableTiming);
    }

    void* zb_ptr = nullptr;
    cudaGetSymbolAddress(&zb_ptr, g_zb);

    const int EB256 = (EE + 255) / 256;
    const int GPB = (NN + 3) / 4;          // fused gathers: 128-thr blocks, warp per node
    const int WPB8 = (NN / 8 + 7) / 8;

    // fork: side stream builds LUT + species-pure prep, overlapping the CSR chain
    cudaEventRecord(evA, 0);
    cudaStreamWaitEvent(s2, evA, 0);
    k_build_table<<<dim3(TBINS, 2), 128, 0, s2>>>(mlp_w0, mlp_w1, mlp_w2);
    k_spec0<<<1, 192, 0, s2>>>(embed_w, w_lin1_s, w_res_s, w_out1, w_out2);
    cudaEventRecord(evB, s2);

    // main chain: CSR build
    cudaMemsetAsync(zb_ptr, 0, (NN + 16 + NODE_BLOCKS) * sizeof(int));
    k_hist<<<EB256, 256>>>(edge_vectors, receivers, species);
    k_scan<<<NODE_BLOCKS, 256>>>();
    k_scatter<<<EB256, 256>>>(edge_vectors, senders, receivers, species);

    // join, then fused layers
    cudaStreamWaitEvent(0, evB, 0);
    k_gfused0<<<GPB, 128>>>(species, w_lin2_s, w_lin2_v);
    k_prep1<<<WPB8, 256>>>(species, w_res_s, w_lin1_s, w_lin1_v);
    k_gfused1<<<GPB, 128>>>(w_lin2_s, out);
}